// round 15
// baseline (speedup 1.0000x reference)
#include <cuda_runtime.h>
#include <cuda_bf16.h>
#include <cstdint>

#define BSZ 512
#define NN  128
#define HX  256
#define HL  64
#define HY  128
#define ROWS (BSZ*NN)          // 65536
#define KXL 320
#define KH  448

typedef __nv_bfloat16 bf16;

// ---------------- scratch ----------------
__device__ float    g_dinv[ROWS];
__device__ unsigned g_mask[(size_t)ROWS*4];
__device__ __align__(16) bf16 g_Thi[(size_t)ROWS*KXL];   // dinv-scaled T, hi plane
__device__ __align__(16) bf16 g_Tlo[(size_t)ROWS*KXL];   // lo plane
__device__ float    g_H [(size_t)ROWS*KXL];              // fp32 H
__device__ float    g_Yc[(size_t)BSZ*HX];
__device__ __align__(16) bf16 g_Wxh[320*256], g_Wxl[320*256];
__device__ __align__(16) bf16 g_W1h[320*256], g_W1l[320*256];
__device__ __align__(16) bf16 g_Wlh[64*64],   g_Wll[64*64];

// ---------------- helpers ----------------
__device__ __forceinline__ uint32_t smem_u32(const void* p) {
    uint32_t a;
    asm("{ .reg .u64 t; cvta.to.shared.u64 t, %1; cvt.u32.u64 %0, t; }" : "=r"(a) : "l"(p));
    return a;
}
__device__ __forceinline__ float warp_sum(float v) {
#pragma unroll
    for (int o = 16; o; o >>= 1) v += __shfl_xor_sync(0xffffffffu, v, o);
    return v;
}
__device__ __forceinline__ void split2(float a, float b, uint32_t& hi, uint32_t& lo) {
    __nv_bfloat162 h = __floats2bfloat162_rn(a, b);
    float ra = a - __bfloat162float(h.x);
    float rb = b - __bfloat162float(h.y);
    __nv_bfloat162 l = __floats2bfloat162_rn(ra, rb);
    hi = *(uint32_t*)&h;
    lo = *(uint32_t*)&l;
}

#define LDSM_X4(R0,R1,R2,R3,ADDR) \
    asm volatile("ldmatrix.sync.aligned.m8n8.x4.shared.b16 {%0,%1,%2,%3}, [%4];" \
        : "=r"(R0), "=r"(R1), "=r"(R2), "=r"(R3) : "r"(ADDR))
#define LDSM_X4T(R0,R1,R2,R3,ADDR) \
    asm volatile("ldmatrix.sync.aligned.m8n8.x4.trans.shared.b16 {%0,%1,%2,%3}, [%4];" \
        : "=r"(R0), "=r"(R1), "=r"(R2), "=r"(R3) : "r"(ADDR))

__device__ __forceinline__ void mma16816(float* c, const uint32_t* a, uint32_t b0, uint32_t b1) {
    asm volatile("mma.sync.aligned.m16n8k16.row.col.f32.bf16.bf16.f32 "
        "{%0,%1,%2,%3}, {%4,%5,%6,%7}, {%8,%9}, {%0,%1,%2,%3};"
        : "+f"(c[0]), "+f"(c[1]), "+f"(c[2]), "+f"(c[3])
        : "r"(a[0]), "r"(a[1]), "r"(a[2]), "r"(a[3]), "r"(b0), "r"(b1));
}

// ---------------- prep: degree + adjacency bitmask ----------------
__global__ void dinv_mask_kernel(const int* __restrict__ E, float* __restrict__ dinv,
                                 unsigned* __restrict__ mask) {
    int t = threadIdx.x, w = t >> 5, l = t & 31;
    size_t row = (size_t)blockIdx.x * 8 + w;
    const int* er = E + row * 256 + 1;
    int cnt = 0;
#pragma unroll
    for (int c = 0; c < 4; c++) {
        unsigned b = __ballot_sync(0xffffffffu, er[(size_t)(c * 32 + l) * 2] != 0);
        if (l == 0) mask[row * 4 + c] = b;
        cnt += __popc(b);
    }
    if (l == 0) dinv[row] = rsqrtf((float)cnt + 1.0f);
}

// ---------------- prep: split weight mats ----------
__global__ void wsplit_all_kernel(const float* __restrict__ Wx, const float* __restrict__ W1,
                                  const float* __restrict__ Wl,
                                  bf16* __restrict__ Wxh, bf16* __restrict__ Wxl,
                                  bf16* __restrict__ W1h, bf16* __restrict__ W1l,
                                  bf16* __restrict__ Wlh, bf16* __restrict__ Wll) {
    int idx = blockIdx.x * 256 + threadIdx.x;
    if (idx >= 167936) return;
    const float* src;
    bf16 *oh, *ol;
    int off;
    if (idx < 81920)       { src = Wx; oh = Wxh; ol = Wxl; off = idx; }
    else if (idx < 163840) { src = W1; oh = W1h; ol = W1l; off = idx - 81920; }
    else                   { src = Wl; oh = Wlh; ol = Wll; off = idx - 163840; }
    float v = src[off];
    bf16 h = __float2bfloat16(v);
    oh[off] = h;
    ol[off] = __float2bfloat16(v - __bfloat162float(h));
}

// ---------------- prep: Yc[b] = y[b] @ W1[320:448] + b1 ----------------
__global__ void yc_kernel(const float* __restrict__ y, const float* __restrict__ W1,
                          const float* __restrict__ b1, float* __restrict__ Yc) {
    __shared__ float ys[128];
    int b = blockIdx.x, n = threadIdx.x;
    if (n < 128) ys[n] = y[b * 128 + n];
    __syncthreads();
    float acc = b1[n];
#pragma unroll 8
    for (int k = 0; k < 128; k++)
        acc = fmaf(ys[k], W1[(size_t)(320 + k) * 256 + n], acc);
    Yc[(size_t)b * 256 + n] = acc;
}

// ---------------- gemm0: 128x128 block, plane-split T store ----------
__global__ void __launch_bounds__(256, 2) gemm0_mma(
    const float* __restrict__ A0, const float* __restrict__ A1,
    const bf16* __restrict__ Bh, const bf16* __restrict__ Bl,
    const float* __restrict__ dinv,
    bf16* __restrict__ Ch, bf16* __restrict__ Cl)
{
    extern __shared__ char sm[];
    bf16* AsH = (bf16*)(sm);
    bf16* AsL = (bf16*)(sm + 12288);
    bf16* BsH = (bf16*)(sm + 24576);
    bf16* BsL = (bf16*)(sm + 33280);
    float* aux = (float*)(sm + 41984);

    const int t = threadIdx.x, lane = t & 31, wid = t >> 5;
    const int wm = wid >> 1, wn = wid & 1;
    const size_t brow = (size_t)blockIdx.y * 128;
    const int bcol = blockIdx.x * 128;

    if (t < 128) aux[t] = dinv[brow + t];

    const uint32_t aOffH = smem_u32(AsH) + ((wm * 32 + (lane & 15)) * 24 + (lane >> 4) * 8) * 2;
    const uint32_t aOffL = aOffH + 12288;
    const uint32_t bOffH = smem_u32(BsH) + ((lane & 15) * 136 + wn * 64 + ((lane >> 4) << 3)) * 2;
    const uint32_t bOffL = bOffH + 8704;

    float acc[2][8][4] = {};
    float4 pa0, pa1;
    uint4 pbh, pbl;
    const int arL = t >> 1, acg = (t & 1) * 8;
    const int bk = t >> 4, bn8 = (t & 15) * 8;

#define LOADG0(k0) do {                                                       \
        int col = (k0) + acg;                                                 \
        const float* s = (col < 256) ? A0 + (brow + arL) * 256 + col          \
                                     : A1 + (brow + arL) * 64 + (col - 256);  \
        pa0 = *(const float4*)s; pa1 = *(const float4*)(s + 4);               \
        pbh = *(const uint4*)(Bh + (size_t)((k0) + bk) * 256 + bcol + bn8);   \
        pbl = *(const uint4*)(Bl + (size_t)((k0) + bk) * 256 + bcol + bn8);   \
    } while (0)

#define STORES0(buf) do {                                                     \
        uint4 ph, pl;                                                         \
        split2(pa0.x, pa0.y, ph.x, pl.x); split2(pa0.z, pa0.w, ph.y, pl.y);   \
        split2(pa1.x, pa1.y, ph.z, pl.z); split2(pa1.z, pa1.w, ph.w, pl.w);   \
        *(uint2*)(AsH + (buf) * 3072 + arL * 24 + acg) = make_uint2(ph.x, ph.y); \
        *(uint2*)(AsH + (buf) * 3072 + arL * 24 + acg + 4) = make_uint2(ph.z, ph.w); \
        *(uint2*)(AsL + (buf) * 3072 + arL * 24 + acg) = make_uint2(pl.x, pl.y); \
        *(uint2*)(AsL + (buf) * 3072 + arL * 24 + acg + 4) = make_uint2(pl.z, pl.w); \
        *(uint4*)(BsH + (buf) * 2176 + bk * 136 + bn8) = pbh;                 \
        *(uint4*)(BsL + (buf) * 2176 + bk * 136 + bn8) = pbl;                 \
    } while (0)

    LOADG0(0);
    int buf = 0;
#pragma unroll 1
    for (int c = 0; c < 20; c++) {
        STORES0(buf);
        if (c + 1 < 20) LOADG0((c + 1) * 16);
        __syncthreads();
        uint32_t ah[2][4], al[2][4];
#pragma unroll
        for (int mt = 0; mt < 2; mt++) {
            LDSM_X4(ah[mt][0], ah[mt][1], ah[mt][2], ah[mt][3], aOffH + buf * 6144 + mt * 768);
            LDSM_X4(al[mt][0], al[mt][1], al[mt][2], al[mt][3], aOffL + buf * 6144 + mt * 768);
        }
#pragma unroll
        for (int np = 0; np < 4; np++) {
            uint32_t bh[4], bl[4];
            LDSM_X4T(bh[0], bh[1], bh[2], bh[3], bOffH + buf * 4352 + np * 32);
            LDSM_X4T(bl[0], bl[1], bl[2], bl[3], bOffL + buf * 4352 + np * 32);
            mma16816(acc[0][np * 2],     ah[0], bh[0], bh[1]);
            mma16816(acc[0][np * 2 + 1], ah[0], bh[2], bh[3]);
            mma16816(acc[1][np * 2],     ah[1], bh[0], bh[1]);
            mma16816(acc[1][np * 2 + 1], ah[1], bh[2], bh[3]);
            mma16816(acc[0][np * 2],     ah[0], bl[0], bl[1]);
            mma16816(acc[0][np * 2 + 1], ah[0], bl[2], bl[3]);
            mma16816(acc[1][np * 2],     ah[1], bl[0], bl[1]);
            mma16816(acc[1][np * 2 + 1], ah[1], bl[2], bl[3]);
            mma16816(acc[0][np * 2],     al[0], bh[0], bh[1]);
            mma16816(acc[0][np * 2 + 1], al[0], bh[2], bh[3]);
            mma16816(acc[1][np * 2],     al[1], bh[0], bh[1]);
            mma16816(acc[1][np * 2 + 1], al[1], bh[2], bh[3]);
        }
        buf ^= 1;
    }

    const int g = lane >> 2, q = (lane & 3) * 2;
#pragma unroll
    for (int mt = 0; mt < 2; mt++) {
        int r0loc = wm * 32 + mt * 16 + g;
        float d0 = aux[r0loc], d1 = aux[r0loc + 8];
#pragma unroll
        for (int nt = 0; nt < 8; nt++) {
            const float* a = acc[mt][nt];
            int col = bcol + wn * 64 + nt * 8 + q;
            size_t r0 = brow + r0loc;
            uint32_t h, l;
            split2(a[0] * d0, a[1] * d0, h, l);
            *(uint32_t*)(Ch + r0 * KXL + col) = h;
            *(uint32_t*)(Cl + r0 * KXL + col) = l;
            split2(a[2] * d1, a[3] * d1, h, l);
            *(uint32_t*)(Ch + (r0 + 8) * KXL + col) = h;
            *(uint32_t*)(Cl + (r0 + 8) * KXL + col) = l;
        }
    }
#undef LOADG0
#undef STORES0
}

// ---------------- gemm1 fused LN: 64x256 block, K=320, Yc as bias (R12) -------------
__global__ void __launch_bounds__(256, 2) gemm1_ln(
    const float* __restrict__ Hm, const float* __restrict__ Yc,
    const bf16* __restrict__ Bh, const bf16* __restrict__ Bl,
    const float* __restrict__ gam, const float* __restrict__ bet,
    float* __restrict__ C)
{
    extern __shared__ char sm[];
    bf16* AsH = (bf16*)(sm);
    bf16* AsL = (bf16*)(sm + 6144);
    bf16* BsH = (bf16*)(sm + 12288);
    bf16* BsL = (bf16*)(sm + 29184);
    float* bias_s = (float*)(sm + 46080);
    float* gam_s  = (float*)(sm + 47104);
    float* bet_s  = (float*)(sm + 48128);
    float* rsum   = (float*)(sm + 49152);
    float* rsq    = (float*)(sm + 50176);
    float* mstd   = (float*)(sm + 51200);

    const int t = threadIdx.x, lane = t & 31, wid = t >> 5;
    const int wm = wid >> 2, wn = wid & 3;
    const size_t brow = (size_t)blockIdx.x * 64;
    const size_t batch = brow >> 7;

    if (t < 256) {
        bias_s[t] = Yc[batch * 256 + t];
        gam_s[t] = gam[t];
        bet_s[t] = bet[t];
    }

    const uint32_t aOffH = smem_u32(AsH) + ((wm * 32 + (lane & 15)) * 24 + (lane >> 4) * 8) * 2;
    const uint32_t aOffL = aOffH + 6144;
    const uint32_t bOffH = smem_u32(BsH) + ((lane & 15) * 264 + wn * 64 + ((lane >> 4) << 3)) * 2;
    const uint32_t bOffL = bOffH + 16896;

    float acc[2][8][4] = {};
    float4 pa;
    uint4 pbh[2], pbl[2];
    const int arL = t >> 2, ac4 = (t & 3) * 4;
    const int bk = t >> 5, bn8 = (t & 31) * 8;

#define LOADG1(k0) do {                                                       \
        pa = *(const float4*)(Hm + (brow + arL) * (size_t)KXL + (k0) + ac4);  \
        _Pragma("unroll")                                                     \
        for (int j = 0; j < 2; j++) {                                         \
            int k = bk + j * 8;                                               \
            pbh[j] = *(const uint4*)(Bh + (size_t)((k0) + k) * 256 + bn8);    \
            pbl[j] = *(const uint4*)(Bl + (size_t)((k0) + k) * 256 + bn8);    \
        }                                                                     \
    } while (0)

#define STORES1(buf) do {                                                     \
        uint2 ph, pl;                                                         \
        split2(pa.x, pa.y, ph.x, pl.x); split2(pa.z, pa.w, ph.y, pl.y);       \
        *(uint2*)(AsH + (buf) * 1536 + arL * 24 + ac4) = ph;                  \
        *(uint2*)(AsL + (buf) * 1536 + arL * 24 + ac4) = pl;                  \
        _Pragma("unroll")                                                     \
        for (int j = 0; j < 2; j++) {                                         \
            int k = bk + j * 8;                                               \
            *(uint4*)(BsH + (buf) * 4224 + k * 264 + bn8) = pbh[j];           \
            *(uint4*)(BsL + (buf) * 4224 + k * 264 + bn8) = pbl[j];           \
        }                                                                     \
    } while (0)

    LOADG1(0);
    int buf = 0;
#pragma unroll 1
    for (int c = 0; c < 20; c++) {
        STORES1(buf);
        if (c + 1 < 20) LOADG1((c + 1) * 16);
        __syncthreads();
        uint32_t ah[2][4], al[2][4];
#pragma unroll
        for (int mt = 0; mt < 2; mt++) {
            LDSM_X4(ah[mt][0], ah[mt][1], ah[mt][2], ah[mt][3], aOffH + buf * 3072 + mt * 768);
            LDSM_X4(al[mt][0], al[mt][1], al[mt][2], al[mt][3], aOffL + buf * 3072 + mt * 768);
        }
#pragma unroll
        for (int np = 0; np < 4; np++) {
            uint32_t bh[4], bl[4];
            LDSM_X4T(bh[0], bh[1], bh[2], bh[3], bOffH + buf * 8448 + np * 32);
            LDSM_X4T(bl[0], bl[1], bl[2], bl[3], bOffL + buf * 8448 + np * 32);
            mma16816(acc[0][np * 2],     ah[0], bh[0], bh[1]);
            mma16816(acc[0][np * 2 + 1], ah[0], bh[2], bh[3]);
            mma16816(acc[1][np * 2],     ah[1], bh[0], bh[1]);
            mma16816(acc[1][np * 2 + 1], ah[1], bh[2], bh[3]);
            mma16816(acc[0][np * 2],     ah[0], bl[0], bl[1]);
            mma16816(acc[0][np * 2 + 1], ah[0], bl[2], bl[3]);
            mma16816(acc[1][np * 2],     ah[1], bl[0], bl[1]);
            mma16816(acc[1][np * 2 + 1], ah[1], bl[2], bl[3]);
            mma16816(acc[0][np * 2],     al[0], bh[0], bh[1]);
            mma16816(acc[0][np * 2 + 1], al[0], bh[2], bh[3]);
            mma16816(acc[1][np * 2],     al[1], bh[0], bh[1]);
            mma16816(acc[1][np * 2 + 1], al[1], bh[2], bh[3]);
        }
        buf ^= 1;
    }

    const int g = lane >> 2, q = (lane & 3) * 2;
#pragma unroll
    for (int mt = 0; mt < 2; mt++) {
#pragma unroll
        for (int hf = 0; hf < 2; hf++) {
            float s = 0.f, qq = 0.f;
#pragma unroll
            for (int nt = 0; nt < 8; nt++) {
                int col = wn * 64 + nt * 8 + q;
                float v0 = fmaxf(acc[mt][nt][hf * 2]     + bias_s[col],     0.f);
                float v1 = fmaxf(acc[mt][nt][hf * 2 + 1] + bias_s[col + 1], 0.f);
                s += v0 + v1; qq += v0 * v0 + v1 * v1;
            }
            s  += __shfl_xor_sync(0xffffffffu, s, 1);
            s  += __shfl_xor_sync(0xffffffffu, s, 2);
            qq += __shfl_xor_sync(0xffffffffu, qq, 1);
            qq += __shfl_xor_sync(0xffffffffu, qq, 2);
            if ((lane & 3) == 0) {
                int row = wm * 32 + mt * 16 + hf * 8 + g;
                rsum[row * 4 + wn] = s;
                rsq [row * 4 + wn] = qq;
            }
        }
    }
    __syncthreads();
    if (t < 64) {
        float S = rsum[t * 4] + rsum[t * 4 + 1] + rsum[t * 4 + 2] + rsum[t * 4 + 3];
        float Q = rsq [t * 4] + rsq [t * 4 + 1] + rsq [t * 4 + 2] + rsq [t * 4 + 3];
        float mean = S * (1.0f / 256.0f);
        float var  = Q * (1.0f / 256.0f) - mean * mean;
        mstd[t * 2]     = mean;
        mstd[t * 2 + 1] = rsqrtf(var + 1e-5f);
    }
    __syncthreads();
#pragma unroll
    for (int mt = 0; mt < 2; mt++)
#pragma unroll
        for (int nt = 0; nt < 8; nt++) {
            const float* a = acc[mt][nt];
            int col = wn * 64 + nt * 8 + q;
            float b0 = bias_s[col], b1 = bias_s[col + 1];
            float g0 = gam_s[col],  g1 = gam_s[col + 1];
            float e0 = bet_s[col],  e1 = bet_s[col + 1];
            int r0 = wm * 32 + mt * 16 + g;
            float m0 = mstd[r0 * 2], s0 = mstd[r0 * 2 + 1];
            float m1 = mstd[(r0 + 8) * 2], s1 = mstd[(r0 + 8) * 2 + 1];
            float v0 = fmaxf(a[0] + b0, 0.f), v1 = fmaxf(a[1] + b1, 0.f);
            float v2 = fmaxf(a[2] + b0, 0.f), v3 = fmaxf(a[3] + b1, 0.f);
            *(float2*)&C[(brow + r0) * (size_t)HX + col] =
                make_float2((v0 - m0) * s0 * g0 + e0, (v1 - m0) * s0 * g1 + e1);
            *(float2*)&C[(brow + r0 + 8) * (size_t)HX + col] =
                make_float2((v2 - m1) * s1 * g0 + e0, (v3 - m1) * s1 * g1 + e1);
        }
#undef LOADG1
#undef STORES1
}

// ---------------- batched (A+I) MMA GEMM: 128x80 block, K-chunk 32, plane-B copies --
__global__ void __launch_bounds__(256, 2) an_mma(
    const unsigned* __restrict__ mask, const float* __restrict__ dinv,
    const bf16* __restrict__ Thi, const bf16* __restrict__ Tlo,
    const float* __restrict__ bx, const float* __restrict__ bl,
    float* __restrict__ H)
{
    extern __shared__ char sm[];
    bf16* As  = (bf16*)(sm);
    bf16* BsH = (bf16*)(sm + 34816);
    bf16* BsL = (bf16*)(sm + 46080);
    float* bias_s = (float*)(sm + 57344);
    float* dinv_s = (float*)(sm + 57664);

    const int t = threadIdx.x, lane = t & 31, wid = t >> 5;
    const int ct = blockIdx.x, b = blockIdx.y;
    const bf16* Tbh = Thi + (size_t)b * 128 * KXL + ct * 80;
    const bf16* Tbl = Tlo + (size_t)b * 128 * KXL + ct * 80;

#pragma unroll
    for (int j = 0; j < 2; j++) {
        int idx = t + j * 256;
        int i = idx >> 2, jg = idx & 3;
        unsigned m = mask[((size_t)b * 128 + i) * 4 + jg];
        uint32_t* dst = (uint32_t*)(As + i * 136 + jg * 32);
#pragma unroll
        for (int p = 0; p < 16; p++) {
            int j0 = jg * 32 + p * 2;
            uint32_t s0 = ((m >> (p * 2)) & 1u) + (j0 == i);
            uint32_t s1 = ((m >> (p * 2 + 1)) & 1u) + (j0 + 1 == i);
            uint32_t v0 = (s0 == 0) ? 0u : ((s0 == 1) ? 0x3F80u : 0x4000u);
            uint32_t v1 = (s1 == 0) ? 0u : ((s1 == 1) ? 0x3F80u : 0x4000u);
            dst[p] = v0 | (v1 << 16);
        }
    }
    if (t < 80) {
        int gcol = ct * 80 + t;
        bias_s[t] = (gcol < 256) ? bx[gcol] : bl[gcol - 256];
    }
    if (t >= 128 && t < 256) dinv_s[t - 128] = dinv[(size_t)b * 128 + (t - 128)];

    const uint32_t aOff = smem_u32(As) + ((wid * 16 + (lane & 15)) * 136 + (lane >> 4) * 8) * 2;
    const uint32_t bOffH = smem_u32(BsH) + ((lane & 15) * 88 + ((lane >> 4) << 3)) * 2;
    const uint32_t bOffL = smem_u32(BsL) + ((lane & 15) * 88 + ((lane >> 4) << 3)) * 2;

    float acc[10][4] = {};
    uint4 pb[3];
    // chunk32: per plane 32 k-rows x 10 uint4 (80 bf16) = 320 slots; 640 total.
    // slot s: plane = s >= 320; r = s - plane*320; k = r/10; c8 = r%10.
    const int s0 = t,         pl0 = 0,            r0i = t;            // t < 256 < 320
    const int s1 = t + 256,   pl1 = (s1 >= 320),  r1i = s1 - pl1 * 320;
    const int s2 = t + 512,   r2i = s2 - 320;     // always plane 1; valid t < 128
    const int k0s = r0i / 10, c0s = r0i % 10;
    const int k1s = r1i / 10, c1s = r1i % 10;
    const int k2s = r2i / 10, c2s = r2i % 10;
    const bool v2 = (t < 128);
    (void)s0; (void)pl0;

#define BLOAD(k0) do {                                                        \
        pb[0] = *(const uint4*)(Tbh + (size_t)((k0) + k0s) * KXL + c0s * 8);  \
        {                                                                     \
            const bf16* src1 = pl1 ? Tbl : Tbh;                               \
            pb[1] = *(const uint4*)(src1 + (size_t)((k0) + k1s) * KXL + c1s * 8); \
        }                                                                     \
        if (v2) pb[2] = *(const uint4*)(Tbl + (size_t)((k0) + k2s) * KXL + c2s * 8); \
    } while (0)

#define BSTORE(buf) do {                                                      \
        *(uint4*)(BsH + (buf) * 2816 + k0s * 88 + c0s * 8) = pb[0];           \
        {                                                                     \
            bf16* dst1 = pl1 ? BsL : BsH;                                     \
            *(uint4*)(dst1 + (buf) * 2816 + k1s * 88 + c1s * 8) = pb[1];      \
        }                                                                     \
        if (v2) *(uint4*)(BsL + (buf) * 2816 + k2s * 88 + c2s * 8) = pb[2];   \
    } while (0)

    BLOAD(0);
    int buf = 0;
#pragma unroll 1
    for (int c = 0; c < 4; c++) {
        BSTORE(buf);
        if (c + 1 < 4) BLOAD((c + 1) * 32);
        __syncthreads();
#pragma unroll
        for (int ks = 0; ks < 2; ks++) {
            uint32_t a[4];
            LDSM_X4(a[0], a[1], a[2], a[3], aOff + (c * 2 + ks) * 32);
#pragma unroll
            for (int pr = 0; pr < 2; pr++) {
                uint32_t bh0[4], bl0[4], bh1[4], bl1[4];
                uint32_t base = buf * 5632 + ks * 2816 + pr * 64;
                LDSM_X4T(bh0[0], bh0[1], bh0[2], bh0[3], bOffH + base);
                LDSM_X4T(bl0[0], bl0[1], bl0[2], bl0[3], bOffL + base);
                LDSM_X4T(bh1[0], bh1[1], bh1[2], bh1[3], bOffH + base + 32);
                LDSM_X4T(bl1[0], bl1[1], bl1[2], bl1[3], bOffL + base + 32);
                float* a0 = acc[pr * 4 + 0];
                float* a1 = acc[pr * 4 + 1];
                float* a2 = acc[pr * 4 + 2];
                float* a3 = acc[pr * 4 + 3];
                mma16816(a0, a, bh0[0], bh0[1]);
                mma16816(a1, a, bh0[2], bh0[3]);
                mma16816(a2, a, bh1[0], bh1[1]);
                mma16816(a3, a, bh1[2], bh1[3]);
                mma16816(a0, a, bl0[0], bl0[1]);
                mma16816(a1, a, bl0[2], bl0[3]);
                mma16816(a2, a, bl1[0], bl1[1]);
                mma16816(a3, a, bl1[2], bl1[3]);
            }
            {
                uint32_t bh[4], blr[4];
                uint32_t base = buf * 5632 + ks * 2816 + 4 * 32;
                LDSM_X4T(bh[0], bh[1], bh[2], bh[3], bOffH + base);
                LDSM_X4T(blr[0], blr[1], blr[2], blr[3], bOffL + base);
                mma16816(acc[8], a, bh[0], bh[1]);
                mma16816(acc[9], a, bh[2], bh[3]);
                mma16816(acc[8], a, blr[0], blr[1]);
                mma16816(acc[9], a, blr[2], blr[3]);
            }
        }
        buf ^= 1;
    }

    const int g = lane >> 2, q = (lane & 3) * 2;
    const int r0loc = wid * 16 + g;
    const float d0 = dinv_s[r0loc], d1 = dinv_s[r0loc + 8];
#pragma unroll
    for (int nt = 0; nt < 10; nt++) {
        const float* a = acc[nt];
        int lcol = nt * 8 + q;
        int gcol = ct * 80 + lcol;
        float b0 = bias_s[lcol], b1 = bias_s[lcol + 1];
        size_t r0 = (size_t)b * 128 + r0loc;
        *(float2*)&H[r0 * KXL + gcol] =
            make_float2(fmaf(a[0], d0, b0), fmaf(a[1], d0, b1));
        *(float2*)&H[(r0 + 8) * KXL + gcol] =
            make_float2(fmaf(a[2], d1, b0), fmaf(a[3], d1, b1));
    }
#undef BLOAD
#undef BSTORE
}

// ---------------- label@Wl via MMA: 128x64, K=64, plane-split store ----------------
__global__ void __launch_bounds__(256) sgemm64_mma(
    const float* __restrict__ A, const bf16* __restrict__ Wlh,
    const bf16* __restrict__ Wll, const float* __restrict__ dinv,
    bf16* __restrict__ Ch, bf16* __restrict__ Cl)
{
    __shared__ __align__(16) bf16 AsH[2 * 3072];
    __shared__ __align__(16) bf16 AsL[2 * 3072];
    __shared__ __align__(16) bf16 BsH[2 * 1152];
    __shared__ __align__(16) bf16 BsL[2 * 1152];
    __shared__ float dinv_s[128];

    const int t = threadIdx.x, lane = t & 31, wid = t >> 5;
    const size_t brow = (size_t)blockIdx.x * 128;
    if (t < 128) dinv_s[t] = dinv[brow + t];

    const uint32_t aOffH = smem_u32(AsH) + ((wid * 16 + (lane & 15)) * 24 + (lane >> 4) * 8) * 2;
    const uint32_t aOffL = smem_u32(AsL) + ((wid * 16 + (lane & 15)) * 24 + (lane >> 4) * 8) * 2;
    const uint32_t bOffH = smem_u32(BsH) + ((lane & 15) * 72 + ((lane >> 4) << 3)) * 2;
    const uint32_t bOffL = smem_u32(BsL) + ((lane & 15) * 72 + ((lane >> 4) << 3)) * 2;

    float acc[8][4] = {};
    float4 pa[2];
    uint4 pb;
    const int ar0 = t >> 2, ac0 = (t & 3) * 4;
    const int ar1 = (t + 256) >> 2, ac1 = ((t + 256) & 3) * 4;
    const int bpl = t >> 7, bkr = (t & 127) >> 3, bc8 = (t & 7) * 8;

#define SLOAD(k0) do {                                                        \
        pa[0] = *(const float4*)(A + (brow + ar0) * 64 + (k0) + ac0);         \
        pa[1] = *(const float4*)(A + (brow + ar1) * 64 + (k0) + ac1);         \
        const bf16* wsrc = bpl ? Wll : Wlh;                                   \
        pb = *(const uint4*)(wsrc + (size_t)((k0) + bkr) * 64 + bc8);         \
    } while (0)

#define SSTORE(buf) do {                                                      \
        uint32_t h0, l0, h1, l1;                                              \
        split2(pa[0].x, pa[0].y, h0, l0); split2(pa[0].z, pa[0].w, h1, l1);   \
        *(uint2*)(AsH + (buf) * 3072 + ar0 * 24 + ac0) = make_uint2(h0, h1);  \
        *(uint2*)(AsL + (buf) * 3072 + ar0 * 24 + ac0) = make_uint2(l0, l1);  \
        split2(pa[1].x, pa[1].y, h0, l0); split2(pa[1].z, pa[1].w, h1, l1);   \
        *(uint2*)(AsH + (buf) * 3072 + ar1 * 24 + ac1) = make_uint2(h0, h1);  \
        *(uint2*)(AsL + (buf) * 3072 + ar1 * 24 + ac1) = make_uint2(l0, l1);  \
        bf16* wdst = bpl ? BsL : BsH;                                         \
        *(uint4*)(wdst + (buf) * 1152 + bkr * 72 + bc8) = pb;                 \
    } while (0)

    SLOAD(0);
    int buf = 0;
#pragma unroll 1
    for (int c = 0; c < 4; c++) {
        SSTORE(buf);
        if (c + 1 < 4) SLOAD((c + 1) * 16);
        __syncthreads();
        uint32_t ah[4], al[4];
        LDSM_X4(ah[0], ah[1], ah[2], ah[3], aOffH + buf * 6144);
        LDSM_X4(al[0], al[1], al[2], al[3], aOffL + buf * 6144);
#pragma unroll
        for (int np = 0; np < 4; np++) {
            uint32_t bh[4], blr[4];
            LDSM_X4T(bh[0], bh[1], bh[2], bh[3], bOffH + buf * 2304 + np * 32);
            LDSM_X4T(blr[0], blr[1], blr[2], blr[3], bOffL + buf * 2304 + np * 32);
            mma16816(acc[np * 2],     ah, bh[0], bh[1]);
            mma16816(acc[np * 2 + 1], ah, bh[2], bh[3]);
            mma16816(acc[np * 2],     ah, blr[0], blr[1]);
            mma16816(acc[np * 2 + 1], ah, blr[2], blr[3]);
            mma16816(acc[np * 2],     al, bh[0], bh[1]);
            mma16816(acc[np * 2 + 1], al, bh[2], bh[3]);
        }
        buf ^= 1;
    }

    const int g = lane >> 2, q = (lane & 3) * 2;
    const int r0loc = wid * 16 + g;
    const float d0 = dinv_s[r0loc], d1 = dinv_s[r0loc + 8];
#pragma unroll
    for (int nt = 0; nt < 8; nt++) {
        const float* a = acc[nt];
        int col = 256 + nt * 8 + q;
        size_t r0 = brow + r0loc;
        uint32_t h, l;
        split2(a[0] * d0, a[1] * d0, h, l);
        *(uint32_t*)(Ch + r0 * KXL + col) = h;
        *(uint32_t*)(Cl + r0 * KXL + col) = l;
        split2(a[2] * d1, a[3] * d1, h, l);
        *(uint32_t*)(Ch + (r0 + 8) * KXL + col) = h;
        *(uint32_t*)(Cl + (r0 + 8) * KXL + col) = l;
    }
#undef SLOAD
#undef SSTORE
}

// ---------------- fused relu(la@W2+b2) + LN(64) ----------------
__global__ void label_out_kernel(const float* __restrict__ H, const float* __restrict__ W2,
                                 const float* __restrict__ b2, const float* __restrict__ g2,
                                 const float* __restrict__ be2, float* __restrict__ out) {
    __shared__ float W2s[64][64];
    __shared__ float las[8][64];
    const int t = threadIdx.x, w = t >> 5, l = t & 31;
#pragma unroll
    for (int i = 0; i < 4; i++) {
        int idx = t + i * 256;
        ((float4*)&W2s[0][0])[idx] = ((const float4*)W2)[idx];
    }
    size_t row = (size_t)blockIdx.x * 8 + w;
    const float* hrow = H + row * KXL + HX;
    las[w][l] = hrow[l];
    las[w][l + 32] = hrow[l + 32];
    __syncthreads();
    float acc0 = 0.f, acc1 = 0.f;
#pragma unroll
    for (int k = 0; k < 64; k++) {
        float v = las[w][k];
        acc0 = fmaf(v, W2s[k][l], acc0);
        acc1 = fmaf(v, W2s[k][l + 32], acc1);
    }
    acc0 = fmaxf(acc0 + b2[l], 0.f);
    acc1 = fmaxf(acc1 + b2[l + 32], 0.f);
    float mean = warp_sum(acc0 + acc1) * (1.0f / 64.0f);
    float sq = warp_sum(acc0 * acc0 + acc1 * acc1) * (1.0f / 64.0f);
    float r = rsqrtf(sq - mean * mean + 1e-5f);
    out[row * HL + l]      = (acc0 - mean) * r * g2[l] + be2[l];
    out[row * HL + l + 32] = (acc1 - mean) * r * g2[l + 32] + be2[l + 32];
}

// ---------------- launcher ----------------
extern "C" void kernel_launch(void* const* d_in, const int* in_sizes, int n_in,
                              void* d_out, int out_size) {
    const float* X     = (const float*)d_in[0];
    const int*   E     = (const int*)d_in[1];
    const float* y     = (const float*)d_in[2];
    const float* label = (const float*)d_in[3];
    const float* Wx  = (const float*)d_in[5];
    const float* bx  = (const float*)d_in[6];
    const float* Wl  = (const float*)d_in[7];
    const float* bl  = (const float*)d_in[8];
    const float* W1  = (const float*)d_in[9];
    const float* b1  = (const float*)d_in[10];
    const float* g1  = (const float*)d_in[11];
    const float* be1 = (const float*)d_in[12];
    const float* W2  = (const float*)d_in[13];
    const float* b2  = (const float*)d_in[14];
    const float* g2  = (const float*)d_in[15];
    const float* be2 = (const float*)d_in[16];
    float* out_X = (float*)d_out;
    float* out_L = out_X + (size_t)ROWS * HX;

    float *pdinv, *pH, *pYc;
    unsigned* pmask;
    bf16 *pThi, *pTlo, *pWxh, *pWxl, *pW1h, *pW1l, *pWlh, *pWll;
    cudaGetSymbolAddress((void**)&pdinv, g_dinv);
    cudaGetSymbolAddress((void**)&pmask, g_mask);
    cudaGetSymbolAddress((void**)&pThi,  g_Thi);
    cudaGetSymbolAddress((void**)&pTlo,  g_Tlo);
    cudaGetSymbolAddress((void**)&pH,    g_H);
    cudaGetSymbolAddress((void**)&pYc,   g_Yc);
    cudaGetSymbolAddress((void**)&pWxh,  g_Wxh);
    cudaGetSymbolAddress((void**)&pWxl,  g_Wxl);
    cudaGetSymbolAddress((void**)&pW1h,  g_W1h);
    cudaGetSymbolAddress((void**)&pW1l,  g_W1l);
    cudaGetSymbolAddress((void**)&pWlh,  g_Wlh);
    cudaGetSymbolAddress((void**)&pWll,  g_Wll);

    const int SMEM0 = 42496;
    const int SMEM1 = 51712;
    const int SMEMA = 58176;
    cudaFuncSetAttribute(gemm0_mma, cudaFuncAttributeMaxDynamicSharedMemorySize, SMEM0);
    cudaFuncSetAttribute(gemm1_ln,  cudaFuncAttributeMaxDynamicSharedMemorySize, SMEM1);
    cudaFuncSetAttribute(an_mma,    cudaFuncAttributeMaxDynamicSharedMemorySize, SMEMA);

    dinv_mask_kernel<<<ROWS / 8, 256>>>(E, pdinv, pmask);
    wsplit_all_kernel<<<(167936 + 255) / 256, 256>>>(Wx, W1, Wl,
                                                     pWxh, pWxl, pW1h, pW1l, pWlh, pWll);
    yc_kernel<<<BSZ, 256>>>(y, W1, b1, pYc);

    gemm0_mma<<<dim3(2, 512), 256, SMEM0>>>(X, label, pWxh, pWxl, pdinv, pThi, pTlo);
    sgemm64_mma<<<512, 256>>>(label, pWlh, pWll, pdinv, pThi, pTlo);

    an_mma<<<dim3(4, BSZ), 256, SMEMA>>>(pmask, pdinv, pThi, pTlo, bx, bl, pH);

    gemm1_ln<<<1024, 256, SMEM1>>>(pH, pYc, pW1h, pW1l, g1, be1, out_X);

    label_out_kernel<<<ROWS / 8, 256>>>(pH, W2, b2, g2, be2, out_L);
}

// round 16
// speedup vs baseline: 1.0416x; 1.0416x over previous
#include <cuda_runtime.h>
#include <cuda_bf16.h>
#include <cstdint>

#define BSZ 512
#define NN  128
#define HX  256
#define HL  64
#define HY  128
#define ROWS (BSZ*NN)          // 65536
#define KXL 320
#define KH  448

typedef __nv_bfloat16 bf16;

// ---------------- scratch ----------------
__device__ float    g_dinv[ROWS];
__device__ unsigned g_mask[(size_t)ROWS*4];
__device__ float    g_T [(size_t)ROWS*KXL];     // 84 MB (dinv-scaled T)
__device__ float    g_H [(size_t)ROWS*KXL];     // 84 MB
__device__ float    g_Yc[(size_t)BSZ*HX];       // per-batch y@W1y + b1
__device__ __align__(16) bf16 g_Wxh[320*256], g_Wxl[320*256];
__device__ __align__(16) bf16 g_W1h[320*256], g_W1l[320*256];
__device__ __align__(16) bf16 g_Wlh[64*64],   g_Wll[64*64];

// ---------------- helpers ----------------
__device__ __forceinline__ uint32_t smem_u32(const void* p) {
    uint32_t a;
    asm("{ .reg .u64 t; cvta.to.shared.u64 t, %1; cvt.u32.u64 %0, t; }" : "=r"(a) : "l"(p));
    return a;
}
__device__ __forceinline__ float warp_sum(float v) {
#pragma unroll
    for (int o = 16; o; o >>= 1) v += __shfl_xor_sync(0xffffffffu, v, o);
    return v;
}
__device__ __forceinline__ void split2(float a, float b, uint32_t& hi, uint32_t& lo) {
    __nv_bfloat162 h = __floats2bfloat162_rn(a, b);
    float ra = a - __bfloat162float(h.x);
    float rb = b - __bfloat162float(h.y);
    __nv_bfloat162 l = __floats2bfloat162_rn(ra, rb);
    hi = *(uint32_t*)&h;
    lo = *(uint32_t*)&l;
}

#define LDSM_X4(R0,R1,R2,R3,ADDR) \
    asm volatile("ldmatrix.sync.aligned.m8n8.x4.shared.b16 {%0,%1,%2,%3}, [%4];" \
        : "=r"(R0), "=r"(R1), "=r"(R2), "=r"(R3) : "r"(ADDR))
#define LDSM_X4T(R0,R1,R2,R3,ADDR) \
    asm volatile("ldmatrix.sync.aligned.m8n8.x4.trans.shared.b16 {%0,%1,%2,%3}, [%4];" \
        : "=r"(R0), "=r"(R1), "=r"(R2), "=r"(R3) : "r"(ADDR))

__device__ __forceinline__ void mma16816(float* c, const uint32_t* a, uint32_t b0, uint32_t b1) {
    asm volatile("mma.sync.aligned.m16n8k16.row.col.f32.bf16.bf16.f32 "
        "{%0,%1,%2,%3}, {%4,%5,%6,%7}, {%8,%9}, {%0,%1,%2,%3};"
        : "+f"(c[0]), "+f"(c[1]), "+f"(c[2]), "+f"(c[3])
        : "r"(a[0]), "r"(a[1]), "r"(a[2]), "r"(a[3]), "r"(b0), "r"(b1));
}

// ---------------- prep: degree + adjacency bitmask ----------------
__global__ void dinv_mask_kernel(const int* __restrict__ E, float* __restrict__ dinv,
                                 unsigned* __restrict__ mask) {
    int t = threadIdx.x, w = t >> 5, l = t & 31;
    size_t row = (size_t)blockIdx.x * 8 + w;
    const int* er = E + row * 256 + 1;
    int cnt = 0;
#pragma unroll
    for (int c = 0; c < 4; c++) {
        unsigned b = __ballot_sync(0xffffffffu, er[(size_t)(c * 32 + l) * 2] != 0);
        if (l == 0) mask[row * 4 + c] = b;
        cnt += __popc(b);
    }
    if (l == 0) dinv[row] = rsqrtf((float)cnt + 1.0f);
}

// ---------------- prep: split weight mats ----------
__global__ void wsplit_all_kernel(const float* __restrict__ Wx, const float* __restrict__ W1,
                                  const float* __restrict__ Wl,
                                  bf16* __restrict__ Wxh, bf16* __restrict__ Wxl,
                                  bf16* __restrict__ W1h, bf16* __restrict__ W1l,
                                  bf16* __restrict__ Wlh, bf16* __restrict__ Wll) {
    int idx = blockIdx.x * 256 + threadIdx.x;
    if (idx >= 167936) return;
    const float* src;
    bf16 *oh, *ol;
    int off;
    if (idx < 81920)       { src = Wx; oh = Wxh; ol = Wxl; off = idx; }
    else if (idx < 163840) { src = W1; oh = W1h; ol = W1l; off = idx - 81920; }
    else                   { src = Wl; oh = Wlh; ol = Wll; off = idx - 163840; }
    float v = src[off];
    bf16 h = __float2bfloat16(v);
    oh[off] = h;
    ol[off] = __float2bfloat16(v - __bfloat162float(h));
}

// ---------------- prep: Yc[b] = y[b] @ W1[320:448] + b1 ----------------
__global__ void yc_kernel(const float* __restrict__ y, const float* __restrict__ W1,
                          const float* __restrict__ b1, float* __restrict__ Yc) {
    __shared__ float ys[128];
    int b = blockIdx.x, n = threadIdx.x;
    if (n < 128) ys[n] = y[b * 128 + n];
    __syncthreads();
    float acc = b1[n];
#pragma unroll 8
    for (int k = 0; k < 128; k++)
        acc = fmaf(ys[k], W1[(size_t)(320 + k) * 256 + n], acc);
    Yc[(size_t)b * 256 + n] = acc;
}

// ---------------- gemm0: 128x128 block, 256 threads, 2 CTAs/SM (R12) ----------
__global__ void __launch_bounds__(256, 2) gemm0_mma(
    const float* __restrict__ A0, const float* __restrict__ A1,
    const bf16* __restrict__ Bh, const bf16* __restrict__ Bl,
    const float* __restrict__ dinv, float* __restrict__ C)
{
    extern __shared__ char sm[];
    bf16* AsH = (bf16*)(sm);
    bf16* AsL = (bf16*)(sm + 12288);
    bf16* BsH = (bf16*)(sm + 24576);
    bf16* BsL = (bf16*)(sm + 33280);
    float* aux = (float*)(sm + 41984);

    const int t = threadIdx.x, lane = t & 31, wid = t >> 5;
    const int wm = wid >> 1, wn = wid & 1;
    const size_t brow = (size_t)blockIdx.y * 128;
    const int bcol = blockIdx.x * 128;

    if (t < 128) aux[t] = dinv[brow + t];

    const uint32_t aOffH = smem_u32(AsH) + ((wm * 32 + (lane & 15)) * 24 + (lane >> 4) * 8) * 2;
    const uint32_t aOffL = aOffH + 12288;
    const uint32_t bOffH = smem_u32(BsH) + ((lane & 15) * 136 + wn * 64 + ((lane >> 4) << 3)) * 2;
    const uint32_t bOffL = bOffH + 8704;

    float acc[2][8][4] = {};
    float4 pa0, pa1;
    uint4 pbh, pbl;
    const int arL = t >> 1, acg = (t & 1) * 8;
    const int bk = t >> 4, bn8 = (t & 15) * 8;

#define LOADG0(k0) do {                                                       \
        int col = (k0) + acg;                                                 \
        const float* s = (col < 256) ? A0 + (brow + arL) * 256 + col          \
                                     : A1 + (brow + arL) * 64 + (col - 256);  \
        pa0 = *(const float4*)s; pa1 = *(const float4*)(s + 4);               \
        pbh = *(const uint4*)(Bh + (size_t)((k0) + bk) * 256 + bcol + bn8);   \
        pbl = *(const uint4*)(Bl + (size_t)((k0) + bk) * 256 + bcol + bn8);   \
    } while (0)

#define STORES0(buf) do {                                                     \
        uint4 ph, pl;                                                         \
        split2(pa0.x, pa0.y, ph.x, pl.x); split2(pa0.z, pa0.w, ph.y, pl.y);   \
        split2(pa1.x, pa1.y, ph.z, pl.z); split2(pa1.z, pa1.w, ph.w, pl.w);   \
        *(uint2*)(AsH + (buf) * 3072 + arL * 24 + acg) = make_uint2(ph.x, ph.y); \
        *(uint2*)(AsH + (buf) * 3072 + arL * 24 + acg + 4) = make_uint2(ph.z, ph.w); \
        *(uint2*)(AsL + (buf) * 3072 + arL * 24 + acg) = make_uint2(pl.x, pl.y); \
        *(uint2*)(AsL + (buf) * 3072 + arL * 24 + acg + 4) = make_uint2(pl.z, pl.w); \
        *(uint4*)(BsH + (buf) * 2176 + bk * 136 + bn8) = pbh;                 \
        *(uint4*)(BsL + (buf) * 2176 + bk * 136 + bn8) = pbl;                 \
    } while (0)

    LOADG0(0);
    int buf = 0;
#pragma unroll 1
    for (int c = 0; c < 20; c++) {
        STORES0(buf);
        if (c + 1 < 20) LOADG0((c + 1) * 16);
        __syncthreads();
        uint32_t ah[2][4], al[2][4];
#pragma unroll
        for (int mt = 0; mt < 2; mt++) {
            LDSM_X4(ah[mt][0], ah[mt][1], ah[mt][2], ah[mt][3], aOffH + buf * 6144 + mt * 768);
            LDSM_X4(al[mt][0], al[mt][1], al[mt][2], al[mt][3], aOffL + buf * 6144 + mt * 768);
        }
#pragma unroll
        for (int np = 0; np < 4; np++) {
            uint32_t bh[4], bl[4];
            LDSM_X4T(bh[0], bh[1], bh[2], bh[3], bOffH + buf * 4352 + np * 32);
            LDSM_X4T(bl[0], bl[1], bl[2], bl[3], bOffL + buf * 4352 + np * 32);
            mma16816(acc[0][np * 2],     ah[0], bh[0], bh[1]);
            mma16816(acc[0][np * 2 + 1], ah[0], bh[2], bh[3]);
            mma16816(acc[1][np * 2],     ah[1], bh[0], bh[1]);
            mma16816(acc[1][np * 2 + 1], ah[1], bh[2], bh[3]);
            mma16816(acc[0][np * 2],     ah[0], bl[0], bl[1]);
            mma16816(acc[0][np * 2 + 1], ah[0], bl[2], bl[3]);
            mma16816(acc[1][np * 2],     ah[1], bl[0], bl[1]);
            mma16816(acc[1][np * 2 + 1], ah[1], bl[2], bl[3]);
            mma16816(acc[0][np * 2],     al[0], bh[0], bh[1]);
            mma16816(acc[0][np * 2 + 1], al[0], bh[2], bh[3]);
            mma16816(acc[1][np * 2],     al[1], bh[0], bh[1]);
            mma16816(acc[1][np * 2 + 1], al[1], bh[2], bh[3]);
        }
        buf ^= 1;
    }

    const int g = lane >> 2, q = (lane & 3) * 2;
#pragma unroll
    for (int mt = 0; mt < 2; mt++) {
        int r0loc = wm * 32 + mt * 16 + g;
        float d0 = aux[r0loc], d1 = aux[r0loc + 8];
#pragma unroll
        for (int nt = 0; nt < 8; nt++) {
            const float* a = acc[mt][nt];
            int col = bcol + wn * 64 + nt * 8 + q;
            size_t r0 = brow + r0loc;
            *(float2*)&C[r0 * KXL + col]       = make_float2(a[0] * d0, a[1] * d0);
            *(float2*)&C[(r0 + 8) * KXL + col] = make_float2(a[2] * d1, a[3] * d1);
        }
    }
#undef LOADG0
#undef STORES0
}

// ---------------- gemm1 fused LN + label_out (merged grid) ----------------
// blockIdx.x <  1024: out_X[brow..brow+64,:] = LN(relu(H@W1[0:320] + Yc))
// blockIdx.x >= 1024: label_out rows (blockIdx.x-1024)*8 .. +8
__global__ void __launch_bounds__(256, 2) gemm1_fused(
    const float* __restrict__ Hm, const float* __restrict__ Yc,
    const bf16* __restrict__ Bh, const bf16* __restrict__ Bl,
    const float* __restrict__ gam, const float* __restrict__ bet,
    const float* __restrict__ W2, const float* __restrict__ b2,
    const float* __restrict__ g2, const float* __restrict__ be2,
    float* __restrict__ C, float* __restrict__ outL)
{
    extern __shared__ char sm[];
    const int t = threadIdx.x, lane = t & 31, wid = t >> 5;

    if (blockIdx.x >= 1024) {
        // ---- label_out path (proven body, dynamic smem) ----
        float* W2s = (float*)(sm);            // 64x64 = 16KB
        float* las = (float*)(sm + 16384);    // 8x64  = 2KB
        const int w = wid, l = lane;
#pragma unroll
        for (int i = 0; i < 4; i++) {
            int idx = t + i * 256;
            ((float4*)W2s)[idx] = ((const float4*)W2)[idx];
        }
        size_t row = (size_t)(blockIdx.x - 1024) * 8 + w;
        const float* hrow = Hm + row * KXL + HX;
        las[w * 64 + l] = hrow[l];
        las[w * 64 + l + 32] = hrow[l + 32];
        __syncthreads();
        float acc0 = 0.f, acc1 = 0.f;
#pragma unroll
        for (int k = 0; k < 64; k++) {
            float v = las[w * 64 + k];
            acc0 = fmaf(v, W2s[k * 64 + l], acc0);
            acc1 = fmaf(v, W2s[k * 64 + l + 32], acc1);
        }
        acc0 = fmaxf(acc0 + b2[l], 0.f);
        acc1 = fmaxf(acc1 + b2[l + 32], 0.f);
        float mean = warp_sum(acc0 + acc1) * (1.0f / 64.0f);
        float sq = warp_sum(acc0 * acc0 + acc1 * acc1) * (1.0f / 64.0f);
        float r = rsqrtf(sq - mean * mean + 1e-5f);
        outL[row * HL + l]      = (acc0 - mean) * r * g2[l] + be2[l];
        outL[row * HL + l + 32] = (acc1 - mean) * r * g2[l + 32] + be2[l + 32];
        return;
    }

    // ---- gemm1 path (R12 proven body) ----
    bf16* AsH = (bf16*)(sm);
    bf16* AsL = (bf16*)(sm + 6144);
    bf16* BsH = (bf16*)(sm + 12288);
    bf16* BsL = (bf16*)(sm + 29184);
    float* bias_s = (float*)(sm + 46080);
    float* gam_s  = (float*)(sm + 47104);
    float* bet_s  = (float*)(sm + 48128);
    float* rsum   = (float*)(sm + 49152);
    float* rsq    = (float*)(sm + 50176);
    float* mstd   = (float*)(sm + 51200);

    const int wm = wid >> 2, wn = wid & 3;
    const size_t brow = (size_t)blockIdx.x * 64;
    const size_t batch = brow >> 7;

    if (t < 256) {
        bias_s[t] = Yc[batch * 256 + t];
        gam_s[t] = gam[t];
        bet_s[t] = bet[t];
    }

    const uint32_t aOffH = smem_u32(AsH) + ((wm * 32 + (lane & 15)) * 24 + (lane >> 4) * 8) * 2;
    const uint32_t aOffL = aOffH + 6144;
    const uint32_t bOffH = smem_u32(BsH) + ((lane & 15) * 264 + wn * 64 + ((lane >> 4) << 3)) * 2;
    const uint32_t bOffL = bOffH + 16896;

    float acc[2][8][4] = {};
    float4 pa;
    uint4 pbh[2], pbl[2];
    const int arL = t >> 2, ac4 = (t & 3) * 4;
    const int bk = t >> 5, bn8 = (t & 31) * 8;

#define LOADG1(k0) do {                                                       \
        pa = *(const float4*)(Hm + (brow + arL) * (size_t)KXL + (k0) + ac4);  \
        _Pragma("unroll")                                                     \
        for (int j = 0; j < 2; j++) {                                         \
            int k = bk + j * 8;                                               \
            pbh[j] = *(const uint4*)(Bh + (size_t)((k0) + k) * 256 + bn8);    \
            pbl[j] = *(const uint4*)(Bl + (size_t)((k0) + k) * 256 + bn8);    \
        }                                                                     \
    } while (0)

#define STORES1(buf) do {                                                     \
        uint2 ph, pl;                                                         \
        split2(pa.x, pa.y, ph.x, pl.x); split2(pa.z, pa.w, ph.y, pl.y);       \
        *(uint2*)(AsH + (buf) * 1536 + arL * 24 + ac4) = ph;                  \
        *(uint2*)(AsL + (buf) * 1536 + arL * 24 + ac4) = pl;                  \
        _Pragma("unroll")                                                     \
        for (int j = 0; j < 2; j++) {                                         \
            int k = bk + j * 8;                                               \
            *(uint4*)(BsH + (buf) * 4224 + k * 264 + bn8) = pbh[j];           \
            *(uint4*)(BsL + (buf) * 4224 + k * 264 + bn8) = pbl[j];           \
        }                                                                     \
    } while (0)

    LOADG1(0);
    int buf = 0;
#pragma unroll 1
    for (int c = 0; c < 20; c++) {
        STORES1(buf);
        if (c + 1 < 20) LOADG1((c + 1) * 16);
        __syncthreads();
        uint32_t ah[2][4], al[2][4];
#pragma unroll
        for (int mt = 0; mt < 2; mt++) {
            LDSM_X4(ah[mt][0], ah[mt][1], ah[mt][2], ah[mt][3], aOffH + buf * 3072 + mt * 768);
            LDSM_X4(al[mt][0], al[mt][1], al[mt][2], al[mt][3], aOffL + buf * 3072 + mt * 768);
        }
#pragma unroll
        for (int np = 0; np < 4; np++) {
            uint32_t bh[4], bl[4];
            LDSM_X4T(bh[0], bh[1], bh[2], bh[3], bOffH + buf * 8448 + np * 32);
            LDSM_X4T(bl[0], bl[1], bl[2], bl[3], bOffL + buf * 8448 + np * 32);
            mma16816(acc[0][np * 2],     ah[0], bh[0], bh[1]);
            mma16816(acc[0][np * 2 + 1], ah[0], bh[2], bh[3]);
            mma16816(acc[1][np * 2],     ah[1], bh[0], bh[1]);
            mma16816(acc[1][np * 2 + 1], ah[1], bh[2], bh[3]);
            mma16816(acc[0][np * 2],     ah[0], bl[0], bl[1]);
            mma16816(acc[0][np * 2 + 1], ah[0], bl[2], bl[3]);
            mma16816(acc[1][np * 2],     ah[1], bl[0], bl[1]);
            mma16816(acc[1][np * 2 + 1], ah[1], bl[2], bl[3]);
            mma16816(acc[0][np * 2],     al[0], bh[0], bh[1]);
            mma16816(acc[0][np * 2 + 1], al[0], bh[2], bh[3]);
            mma16816(acc[1][np * 2],     al[1], bh[0], bh[1]);
            mma16816(acc[1][np * 2 + 1], al[1], bh[2], bh[3]);
        }
        buf ^= 1;
    }

    const int g = lane >> 2, q = (lane & 3) * 2;
#pragma unroll
    for (int mt = 0; mt < 2; mt++) {
#pragma unroll
        for (int hf = 0; hf < 2; hf++) {
            float s = 0.f, qq = 0.f;
#pragma unroll
            for (int nt = 0; nt < 8; nt++) {
                int col = wn * 64 + nt * 8 + q;
                float v0 = fmaxf(acc[mt][nt][hf * 2]     + bias_s[col],     0.f);
                float v1 = fmaxf(acc[mt][nt][hf * 2 + 1] + bias_s[col + 1], 0.f);
                s += v0 + v1; qq += v0 * v0 + v1 * v1;
            }
            s  += __shfl_xor_sync(0xffffffffu, s, 1);
            s  += __shfl_xor_sync(0xffffffffu, s, 2);
            qq += __shfl_xor_sync(0xffffffffu, qq, 1);
            qq += __shfl_xor_sync(0xffffffffu, qq, 2);
            if ((lane & 3) == 0) {
                int row = wm * 32 + mt * 16 + hf * 8 + g;
                rsum[row * 4 + wn] = s;
                rsq [row * 4 + wn] = qq;
            }
        }
    }
    __syncthreads();
    if (t < 64) {
        float S = rsum[t * 4] + rsum[t * 4 + 1] + rsum[t * 4 + 2] + rsum[t * 4 + 3];
        float Q = rsq [t * 4] + rsq [t * 4 + 1] + rsq [t * 4 + 2] + rsq [t * 4 + 3];
        float mean = S * (1.0f / 256.0f);
        float var  = Q * (1.0f / 256.0f) - mean * mean;
        mstd[t * 2]     = mean;
        mstd[t * 2 + 1] = rsqrtf(var + 1e-5f);
    }
    __syncthreads();
#pragma unroll
    for (int mt = 0; mt < 2; mt++)
#pragma unroll
        for (int nt = 0; nt < 8; nt++) {
            const float* a = acc[mt][nt];
            int col = wn * 64 + nt * 8 + q;
            float b0 = bias_s[col], b1 = bias_s[col + 1];
            float g0 = gam_s[col],  g1 = gam_s[col + 1];
            float e0 = bet_s[col],  e1 = bet_s[col + 1];
            int r0 = wm * 32 + mt * 16 + g;
            float m0 = mstd[r0 * 2], s0 = mstd[r0 * 2 + 1];
            float m1 = mstd[(r0 + 8) * 2], s1 = mstd[(r0 + 8) * 2 + 1];
            float v0 = fmaxf(a[0] + b0, 0.f), v1 = fmaxf(a[1] + b1, 0.f);
            float v2 = fmaxf(a[2] + b0, 0.f), v3 = fmaxf(a[3] + b1, 0.f);
            *(float2*)&C[(brow + r0) * (size_t)HX + col] =
                make_float2((v0 - m0) * s0 * g0 + e0, (v1 - m0) * s0 * g1 + e1);
            *(float2*)&C[(brow + r0 + 8) * (size_t)HX + col] =
                make_float2((v2 - m1) * s1 * g0 + e0, (v3 - m1) * s1 * g1 + e1);
        }
#undef LOADG1
#undef STORES1
}

// ---------------- batched (A+I) MMA GEMM: 128x80 block, K-chunk 32 (R12) -----------
__global__ void __launch_bounds__(256, 2) an_mma(
    const unsigned* __restrict__ mask, const float* __restrict__ dinv,
    const float* __restrict__ T,
    const float* __restrict__ bx, const float* __restrict__ bl,
    float* __restrict__ H)
{
    extern __shared__ char sm[];
    bf16* As  = (bf16*)(sm);
    bf16* BsH = (bf16*)(sm + 34816);
    bf16* BsL = (bf16*)(sm + 46080);
    float* bias_s = (float*)(sm + 57344);
    float* dinv_s = (float*)(sm + 57664);

    const int t = threadIdx.x, lane = t & 31, wid = t >> 5;
    const int ct = blockIdx.x, b = blockIdx.y;
    const float* Tb = T + (size_t)b * 128 * KXL + ct * 80;

#pragma unroll
    for (int j = 0; j < 2; j++) {
        int idx = t + j * 256;
        int i = idx >> 2, jg = idx & 3;
        unsigned m = mask[((size_t)b * 128 + i) * 4 + jg];
        uint32_t* dst = (uint32_t*)(As + i * 136 + jg * 32);
#pragma unroll
        for (int p = 0; p < 16; p++) {
            int j0 = jg * 32 + p * 2;
            uint32_t s0 = ((m >> (p * 2)) & 1u) + (j0 == i);
            uint32_t s1 = ((m >> (p * 2 + 1)) & 1u) + (j0 + 1 == i);
            uint32_t v0 = (s0 == 0) ? 0u : ((s0 == 1) ? 0x3F80u : 0x4000u);
            uint32_t v1 = (s1 == 0) ? 0u : ((s1 == 1) ? 0x3F80u : 0x4000u);
            dst[p] = v0 | (v1 << 16);
        }
    }
    if (t < 80) {
        int gcol = ct * 80 + t;
        bias_s[t] = (gcol < 256) ? bx[gcol] : bl[gcol - 256];
    }
    if (t >= 128 && t < 256) dinv_s[t - 128] = dinv[(size_t)b * 128 + (t - 128)];

    const uint32_t aOff = smem_u32(As) + ((wid * 16 + (lane & 15)) * 136 + (lane >> 4) * 8) * 2;
    const uint32_t bOffH = smem_u32(BsH) + ((lane & 15) * 88 + ((lane >> 4) << 3)) * 2;
    const uint32_t bOffL = smem_u32(BsL) + ((lane & 15) * 88 + ((lane >> 4) << 3)) * 2;

    float acc[10][4] = {};
    float4 pb[3];
    const int k_0 = t / 20,           c4_0 = t % 20;
    const int k_1 = (t + 256) / 20,   c4_1 = (t + 256) % 20;
    const int k_2 = (t + 512) / 20,   c4_2 = (t + 512) % 20;
    const bool v2 = (t < 128);

#define BLOAD(k0) do {                                                        \
        pb[0] = *(const float4*)(Tb + (size_t)((k0) + k_0) * KXL + c4_0 * 4); \
        pb[1] = *(const float4*)(Tb + (size_t)((k0) + k_1) * KXL + c4_1 * 4); \
        if (v2) pb[2] = *(const float4*)(Tb + (size_t)((k0) + k_2) * KXL + c4_2 * 4); \
    } while (0)

#define BSTORE(buf) do {                                                      \
        uint32_t h0, l0, h1, l1;                                              \
        split2(pb[0].x, pb[0].y, h0, l0); split2(pb[0].z, pb[0].w, h1, l1);   \
        *(uint2*)(BsH + (buf) * 2816 + k_0 * 88 + c4_0 * 4) = make_uint2(h0, h1); \
        *(uint2*)(BsL + (buf) * 2816 + k_0 * 88 + c4_0 * 4) = make_uint2(l0, l1); \
        split2(pb[1].x, pb[1].y, h0, l0); split2(pb[1].z, pb[1].w, h1, l1);   \
        *(uint2*)(BsH + (buf) * 2816 + k_1 * 88 + c4_1 * 4) = make_uint2(h0, h1); \
        *(uint2*)(BsL + (buf) * 2816 + k_1 * 88 + c4_1 * 4) = make_uint2(l0, l1); \
        if (v2) {                                                             \
            split2(pb[2].x, pb[2].y, h0, l0); split2(pb[2].z, pb[2].w, h1, l1); \
            *(uint2*)(BsH + (buf) * 2816 + k_2 * 88 + c4_2 * 4) = make_uint2(h0, h1); \
            *(uint2*)(BsL + (buf) * 2816 + k_2 * 88 + c4_2 * 4) = make_uint2(l0, l1); \
        }                                                                     \
    } while (0)

    BLOAD(0);
    int buf = 0;
#pragma unroll 1
    for (int c = 0; c < 4; c++) {
        BSTORE(buf);
        if (c + 1 < 4) BLOAD((c + 1) * 32);
        __syncthreads();
#pragma unroll
        for (int ks = 0; ks < 2; ks++) {
            uint32_t a[4];
            LDSM_X4(a[0], a[1], a[2], a[3], aOff + (c * 2 + ks) * 32);
#pragma unroll
            for (int pr = 0; pr < 2; pr++) {
                uint32_t bh0[4], bl0[4], bh1[4], bl1[4];
                uint32_t base = buf * 5632 + ks * 2816 + pr * 64;
                LDSM_X4T(bh0[0], bh0[1], bh0[2], bh0[3], bOffH + base);
                LDSM_X4T(bl0[0], bl0[1], bl0[2], bl0[3], bOffL + base);
                LDSM_X4T(bh1[0], bh1[1], bh1[2], bh1[3], bOffH + base + 32);
                LDSM_X4T(bl1[0], bl1[1], bl1[2], bl1[3], bOffL + base + 32);
                float* a0 = acc[pr * 4 + 0];
                float* a1 = acc[pr * 4 + 1];
                float* a2 = acc[pr * 4 + 2];
                float* a3 = acc[pr * 4 + 3];
                mma16816(a0, a, bh0[0], bh0[1]);
                mma16816(a1, a, bh0[2], bh0[3]);
                mma16816(a2, a, bh1[0], bh1[1]);
                mma16816(a3, a, bh1[2], bh1[3]);
                mma16816(a0, a, bl0[0], bl0[1]);
                mma16816(a1, a, bl0[2], bl0[3]);
                mma16816(a2, a, bl1[0], bl1[1]);
                mma16816(a3, a, bl1[2], bl1[3]);
            }
            {
                uint32_t bh[4], blr[4];
                uint32_t base = buf * 5632 + ks * 2816 + 4 * 32;
                LDSM_X4T(bh[0], bh[1], bh[2], bh[3], bOffH + base);
                LDSM_X4T(blr[0], blr[1], blr[2], blr[3], bOffL + base);
                mma16816(acc[8], a, bh[0], bh[1]);
                mma16816(acc[9], a, bh[2], bh[3]);
                mma16816(acc[8], a, blr[0], blr[1]);
                mma16816(acc[9], a, blr[2], blr[3]);
            }
        }
        buf ^= 1;
    }

    const int g = lane >> 2, q = (lane & 3) * 2;
    const int r0loc = wid * 16 + g;
    const float d0 = dinv_s[r0loc], d1 = dinv_s[r0loc + 8];
#pragma unroll
    for (int nt = 0; nt < 10; nt++) {
        const float* a = acc[nt];
        int lcol = nt * 8 + q;
        int gcol = ct * 80 + lcol;
        float b0 = bias_s[lcol], b1 = bias_s[lcol + 1];
        size_t r0 = (size_t)b * 128 + r0loc;
        *(float2*)&H[r0 * KXL + gcol] =
            make_float2(fmaf(a[0], d0, b0), fmaf(a[1], d0, b1));
        *(float2*)&H[(r0 + 8) * KXL + gcol] =
            make_float2(fmaf(a[2], d1, b0), fmaf(a[3], d1, b1));
    }
#undef BLOAD
#undef BSTORE
}

// ---------------- label@Wl via MMA: 128x64 block, K=64, dinv-scaled (R12) ----------
__global__ void __launch_bounds__(256) sgemm64_mma(
    const float* __restrict__ A, const bf16* __restrict__ Wlh,
    const bf16* __restrict__ Wll, const float* __restrict__ dinv,
    float* __restrict__ C)
{
    __shared__ __align__(16) bf16 AsH[2 * 3072];
    __shared__ __align__(16) bf16 AsL[2 * 3072];
    __shared__ __align__(16) bf16 BsH[2 * 1152];
    __shared__ __align__(16) bf16 BsL[2 * 1152];
    __shared__ float dinv_s[128];

    const int t = threadIdx.x, lane = t & 31, wid = t >> 5;
    const size_t brow = (size_t)blockIdx.x * 128;
    if (t < 128) dinv_s[t] = dinv[brow + t];

    const uint32_t aOffH = smem_u32(AsH) + ((wid * 16 + (lane & 15)) * 24 + (lane >> 4) * 8) * 2;
    const uint32_t aOffL = smem_u32(AsL) + ((wid * 16 + (lane & 15)) * 24 + (lane >> 4) * 8) * 2;
    const uint32_t bOffH = smem_u32(BsH) + ((lane & 15) * 72 + ((lane >> 4) << 3)) * 2;
    const uint32_t bOffL = smem_u32(BsL) + ((lane & 15) * 72 + ((lane >> 4) << 3)) * 2;

    float acc[8][4] = {};
    float4 pa[2];
    uint4 pb;
    const int ar0 = t >> 2, ac0 = (t & 3) * 4;
    const int ar1 = (t + 256) >> 2, ac1 = ((t + 256) & 3) * 4;
    const int bpl = t >> 7, bkr = (t & 127) >> 3, bc8 = (t & 7) * 8;

#define SLOAD(k0) do {                                                        \
        pa[0] = *(const float4*)(A + (brow + ar0) * 64 + (k0) + ac0);         \
        pa[1] = *(const float4*)(A + (brow + ar1) * 64 + (k0) + ac1);         \
        const bf16* wsrc = bpl ? Wll : Wlh;                                   \
        pb = *(const uint4*)(wsrc + (size_t)((k0) + bkr) * 64 + bc8);         \
    } while (0)

#define SSTORE(buf) do {                                                      \
        uint32_t h0, l0, h1, l1;                                              \
        split2(pa[0].x, pa[0].y, h0, l0); split2(pa[0].z, pa[0].w, h1, l1);   \
        *(uint2*)(AsH + (buf) * 3072 + ar0 * 24 + ac0) = make_uint2(h0, h1);  \
        *(uint2*)(AsL + (buf) * 3072 + ar0 * 24 + ac0) = make_uint2(l0, l1);  \
        split2(pa[1].x, pa[1].y, h0, l0); split2(pa[1].z, pa[1].w, h1, l1);   \
        *(uint2*)(AsH + (buf) * 3072 + ar1 * 24 + ac1) = make_uint2(h0, h1);  \
        *(uint2*)(AsL + (buf) * 3072 + ar1 * 24 + ac1) = make_uint2(l0, l1);  \
        bf16* wdst = bpl ? BsL : BsH;                                         \
        *(uint4*)(wdst + (buf) * 1152 + bkr * 72 + bc8) = pb;                 \
    } while (0)

    SLOAD(0);
    int buf = 0;
#pragma unroll 1
    for (int c = 0; c < 4; c++) {
        SSTORE(buf);
        if (c + 1 < 4) SLOAD((c + 1) * 16);
        __syncthreads();
        uint32_t ah[4], al[4];
        LDSM_X4(ah[0], ah[1], ah[2], ah[3], aOffH + buf * 6144);
        LDSM_X4(al[0], al[1], al[2], al[3], aOffL + buf * 6144);
#pragma unroll
        for (int np = 0; np < 4; np++) {
            uint32_t bh[4], blr[4];
            LDSM_X4T(bh[0], bh[1], bh[2], bh[3], bOffH + buf * 2304 + np * 32);
            LDSM_X4T(blr[0], blr[1], blr[2], blr[3], bOffL + buf * 2304 + np * 32);
            mma16816(acc[np * 2],     ah, bh[0], bh[1]);
            mma16816(acc[np * 2 + 1], ah, bh[2], bh[3]);
            mma16816(acc[np * 2],     ah, blr[0], blr[1]);
            mma16816(acc[np * 2 + 1], ah, blr[2], blr[3]);
            mma16816(acc[np * 2],     al, bh[0], bh[1]);
            mma16816(acc[np * 2 + 1], al, bh[2], bh[3]);
        }
        buf ^= 1;
    }

    const int g = lane >> 2, q = (lane & 3) * 2;
    const int r0loc = wid * 16 + g;
    const float d0 = dinv_s[r0loc], d1 = dinv_s[r0loc + 8];
#pragma unroll
    for (int nt = 0; nt < 8; nt++) {
        const float* a = acc[nt];
        int col = nt * 8 + q;
        size_t r0 = brow + r0loc;
        *(float2*)&C[r0 * KXL + 256 + col]       = make_float2(a[0] * d0, a[1] * d0);
        *(float2*)&C[(r0 + 8) * KXL + 256 + col] = make_float2(a[2] * d1, a[3] * d1);
    }
#undef SLOAD
#undef SSTORE
}

// ---------------- launcher ----------------
extern "C" void kernel_launch(void* const* d_in, const int* in_sizes, int n_in,
                              void* d_out, int out_size) {
    const float* X     = (const float*)d_in[0];
    const int*   E     = (const int*)d_in[1];
    const float* y     = (const float*)d_in[2];
    const float* label = (const float*)d_in[3];
    const float* Wx  = (const float*)d_in[5];
    const float* bx  = (const float*)d_in[6];
    const float* Wl  = (const float*)d_in[7];
    const float* bl  = (const float*)d_in[8];
    const float* W1  = (const float*)d_in[9];
    const float* b1  = (const float*)d_in[10];
    const float* g1  = (const float*)d_in[11];
    const float* be1 = (const float*)d_in[12];
    const float* W2  = (const float*)d_in[13];
    const float* b2  = (const float*)d_in[14];
    const float* g2  = (const float*)d_in[15];
    const float* be2 = (const float*)d_in[16];
    float* out_X = (float*)d_out;
    float* out_L = out_X + (size_t)ROWS * HX;

    float *pdinv, *pT, *pH, *pYc;
    unsigned* pmask;
    bf16 *pWxh, *pWxl, *pW1h, *pW1l, *pWlh, *pWll;
    cudaGetSymbolAddress((void**)&pdinv, g_dinv);
    cudaGetSymbolAddress((void**)&pmask, g_mask);
    cudaGetSymbolAddress((void**)&pT,    g_T);
    cudaGetSymbolAddress((void**)&pH,    g_H);
    cudaGetSymbolAddress((void**)&pYc,   g_Yc);
    cudaGetSymbolAddress((void**)&pWxh,  g_Wxh);
    cudaGetSymbolAddress((void**)&pWxl,  g_Wxl);
    cudaGetSymbolAddress((void**)&pW1h,  g_W1h);
    cudaGetSymbolAddress((void**)&pW1l,  g_W1l);
    cudaGetSymbolAddress((void**)&pWlh,  g_Wlh);
    cudaGetSymbolAddress((void**)&pWll,  g_Wll);

    const int SMEM0 = 42496;
    const int SMEM1 = 51712;
    const int SMEMA = 58176;
    cudaFuncSetAttribute(gemm0_mma,   cudaFuncAttributeMaxDynamicSharedMemorySize, SMEM0);
    cudaFuncSetAttribute(gemm1_fused, cudaFuncAttributeMaxDynamicSharedMemorySize, SMEM1);
    cudaFuncSetAttribute(an_mma,      cudaFuncAttributeMaxDynamicSharedMemorySize, SMEMA);

    dinv_mask_kernel<<<ROWS / 8, 256>>>(E, pdinv, pmask);
    wsplit_all_kernel<<<(167936 + 255) / 256, 256>>>(Wx, W1, Wl,
                                                     pWxh, pWxl, pW1h, pW1l, pWlh, pWll);
    yc_kernel<<<BSZ, 256>>>(y, W1, b1, pYc);

    gemm0_mma<<<dim3(2, 512), 256, SMEM0>>>(X, label, pWxh, pWxl, pdinv, pT);
    sgemm64_mma<<<512, 256>>>(label, pWlh, pWll, pdinv, pT);

    an_mma<<<dim3(4, BSZ), 256, SMEMA>>>(pmask, pdinv, pT, bx, bl, pH);

    gemm1_fused<<<1024 + ROWS / 8, 256, SMEM1>>>(pH, pYc, pW1h, pW1l, g1, be1,
                                                 W2, b2, g2, be2, out_X, out_L);
}

// round 17
// speedup vs baseline: 1.0506x; 1.0086x over previous
#include <cuda_runtime.h>
#include <cuda_bf16.h>
#include <cstdint>

#define BSZ 512
#define NN  128
#define HX  256
#define HL  64
#define HY  128
#define ROWS (BSZ*NN)          // 65536
#define KXL 320
#define KH  448

typedef __nv_bfloat16 bf16;

// ---------------- scratch ----------------
__device__ float    g_dinv[ROWS];
__device__ unsigned g_mask[(size_t)ROWS*4];
__device__ float    g_T [(size_t)ROWS*KXL];     // 84 MB (dinv-scaled T)
__device__ float    g_H [(size_t)ROWS*KXL];     // 84 MB
__device__ float    g_Yc[(size_t)BSZ*HX];       // per-batch y@W1y + b1
__device__ __align__(16) bf16 g_Wxh[320*256], g_Wxl[320*256];
__device__ __align__(16) bf16 g_W1h[320*256], g_W1l[320*256];
__device__ __align__(16) bf16 g_Wlh[64*64],   g_Wll[64*64];

// ---------------- helpers ----------------
__device__ __forceinline__ uint32_t smem_u32(const void* p) {
    uint32_t a;
    asm("{ .reg .u64 t; cvta.to.shared.u64 t, %1; cvt.u32.u64 %0, t; }" : "=r"(a) : "l"(p));
    return a;
}
__device__ __forceinline__ float warp_sum(float v) {
#pragma unroll
    for (int o = 16; o; o >>= 1) v += __shfl_xor_sync(0xffffffffu, v, o);
    return v;
}
__device__ __forceinline__ void split2(float a, float b, uint32_t& hi, uint32_t& lo) {
    __nv_bfloat162 h = __floats2bfloat162_rn(a, b);
    float ra = a - __bfloat162float(h.x);
    float rb = b - __bfloat162float(h.y);
    __nv_bfloat162 l = __floats2bfloat162_rn(ra, rb);
    hi = *(uint32_t*)&h;
    lo = *(uint32_t*)&l;
}

#define LDSM_X4(R0,R1,R2,R3,ADDR) \
    asm volatile("ldmatrix.sync.aligned.m8n8.x4.shared.b16 {%0,%1,%2,%3}, [%4];" \
        : "=r"(R0), "=r"(R1), "=r"(R2), "=r"(R3) : "r"(ADDR))
#define LDSM_X4T(R0,R1,R2,R3,ADDR) \
    asm volatile("ldmatrix.sync.aligned.m8n8.x4.trans.shared.b16 {%0,%1,%2,%3}, [%4];" \
        : "=r"(R0), "=r"(R1), "=r"(R2), "=r"(R3) : "r"(ADDR))

__device__ __forceinline__ void mma16816(float* c, const uint32_t* a, uint32_t b0, uint32_t b1) {
    asm volatile("mma.sync.aligned.m16n8k16.row.col.f32.bf16.bf16.f32 "
        "{%0,%1,%2,%3}, {%4,%5,%6,%7}, {%8,%9}, {%0,%1,%2,%3};"
        : "+f"(c[0]), "+f"(c[1]), "+f"(c[2]), "+f"(c[3])
        : "r"(a[0]), "r"(a[1]), "r"(a[2]), "r"(a[3]), "r"(b0), "r"(b1));
}

// ---------------- unified prep kernel ----------------
// blocks [0, 8192): dinv+mask (8 rows each)
// blocks [8192, 8848): weight split (167936 elems)
// blocks [8848, 9360): Yc per batch
__global__ void prep_all_kernel(
    const int* __restrict__ E, float* __restrict__ dinv, unsigned* __restrict__ mask,
    const float* __restrict__ Wx, const float* __restrict__ W1, const float* __restrict__ Wl,
    const float* __restrict__ y, const float* __restrict__ b1,
    bf16* __restrict__ Wxh, bf16* __restrict__ Wxl,
    bf16* __restrict__ W1h, bf16* __restrict__ W1l,
    bf16* __restrict__ Wlh, bf16* __restrict__ Wll,
    float* __restrict__ Yc)
{
    if (blockIdx.x < 8192) {
        int t = threadIdx.x, w = t >> 5, l = t & 31;
        size_t row = (size_t)blockIdx.x * 8 + w;
        const int* er = E + row * 256 + 1;
        int cnt = 0;
#pragma unroll
        for (int c = 0; c < 4; c++) {
            unsigned b = __ballot_sync(0xffffffffu, er[(size_t)(c * 32 + l) * 2] != 0);
            if (l == 0) mask[row * 4 + c] = b;
            cnt += __popc(b);
        }
        if (l == 0) dinv[row] = rsqrtf((float)cnt + 1.0f);
    } else if (blockIdx.x < 8848) {
        int idx = (blockIdx.x - 8192) * 256 + threadIdx.x;
        if (idx >= 167936) return;
        const float* src;
        bf16 *oh, *ol;
        int off;
        if (idx < 81920)       { src = Wx; oh = Wxh; ol = Wxl; off = idx; }
        else if (idx < 163840) { src = W1; oh = W1h; ol = W1l; off = idx - 81920; }
        else                   { src = Wl; oh = Wlh; ol = Wll; off = idx - 163840; }
        float v = src[off];
        bf16 h = __float2bfloat16(v);
        oh[off] = h;
        ol[off] = __float2bfloat16(v - __bfloat162float(h));
    } else {
        __shared__ float ys[128];
        int b = blockIdx.x - 8848, n = threadIdx.x;
        if (n < 128) ys[n] = y[b * 128 + n];
        __syncthreads();
        float acc = b1[n];
#pragma unroll 8
        for (int k = 0; k < 128; k++)
            acc = fmaf(ys[k], W1[(size_t)(320 + k) * 256 + n], acc);
        Yc[(size_t)b * 256 + n] = acc;
    }
}

// ---------------- gemm0: 128x128 block, 256 threads, 2 CTAs/SM (R12) ----------
__global__ void __launch_bounds__(256, 2) gemm0_mma(
    const float* __restrict__ A0, const float* __restrict__ A1,
    const bf16* __restrict__ Bh, const bf16* __restrict__ Bl,
    const float* __restrict__ dinv, float* __restrict__ C)
{
    extern __shared__ char sm[];
    bf16* AsH = (bf16*)(sm);
    bf16* AsL = (bf16*)(sm + 12288);
    bf16* BsH = (bf16*)(sm + 24576);
    bf16* BsL = (bf16*)(sm + 33280);
    float* aux = (float*)(sm + 41984);

    const int t = threadIdx.x, lane = t & 31, wid = t >> 5;
    const int wm = wid >> 1, wn = wid & 1;
    const size_t brow = (size_t)blockIdx.y * 128;
    const int bcol = blockIdx.x * 128;

    if (t < 128) aux[t] = dinv[brow + t];

    const uint32_t aOffH = smem_u32(AsH) + ((wm * 32 + (lane & 15)) * 24 + (lane >> 4) * 8) * 2;
    const uint32_t aOffL = aOffH + 12288;
    const uint32_t bOffH = smem_u32(BsH) + ((lane & 15) * 136 + wn * 64 + ((lane >> 4) << 3)) * 2;
    const uint32_t bOffL = bOffH + 8704;

    float acc[2][8][4] = {};
    float4 pa0, pa1;
    uint4 pbh, pbl;
    const int arL = t >> 1, acg = (t & 1) * 8;
    const int bk = t >> 4, bn8 = (t & 15) * 8;

#define LOADG0(k0) do {                                                       \
        int col = (k0) + acg;                                                 \
        const float* s = (col < 256) ? A0 + (brow + arL) * 256 + col          \
                                     : A1 + (brow + arL) * 64 + (col - 256);  \
        pa0 = *(const float4*)s; pa1 = *(const float4*)(s + 4);               \
        pbh = *(const uint4*)(Bh + (size_t)((k0) + bk) * 256 + bcol + bn8);   \
        pbl = *(const uint4*)(Bl + (size_t)((k0) + bk) * 256 + bcol + bn8);   \
    } while (0)

#define STORES0(buf) do {                                                     \
        uint4 ph, pl;                                                         \
        split2(pa0.x, pa0.y, ph.x, pl.x); split2(pa0.z, pa0.w, ph.y, pl.y);   \
        split2(pa1.x, pa1.y, ph.z, pl.z); split2(pa1.z, pa1.w, ph.w, pl.w);   \
        *(uint2*)(AsH + (buf) * 3072 + arL * 24 + acg) = make_uint2(ph.x, ph.y); \
        *(uint2*)(AsH + (buf) * 3072 + arL * 24 + acg + 4) = make_uint2(ph.z, ph.w); \
        *(uint2*)(AsL + (buf) * 3072 + arL * 24 + acg) = make_uint2(pl.x, pl.y); \
        *(uint2*)(AsL + (buf) * 3072 + arL * 24 + acg + 4) = make_uint2(pl.z, pl.w); \
        *(uint4*)(BsH + (buf) * 2176 + bk * 136 + bn8) = pbh;                 \
        *(uint4*)(BsL + (buf) * 2176 + bk * 136 + bn8) = pbl;                 \
    } while (0)

    LOADG0(0);
    int buf = 0;
#pragma unroll 1
    for (int c = 0; c < 20; c++) {
        STORES0(buf);
        if (c + 1 < 20) LOADG0((c + 1) * 16);
        __syncthreads();
        uint32_t ah[2][4], al[2][4];
#pragma unroll
        for (int mt = 0; mt < 2; mt++) {
            LDSM_X4(ah[mt][0], ah[mt][1], ah[mt][2], ah[mt][3], aOffH + buf * 6144 + mt * 768);
            LDSM_X4(al[mt][0], al[mt][1], al[mt][2], al[mt][3], aOffL + buf * 6144 + mt * 768);
        }
#pragma unroll
        for (int np = 0; np < 4; np++) {
            uint32_t bh[4], bl[4];
            LDSM_X4T(bh[0], bh[1], bh[2], bh[3], bOffH + buf * 4352 + np * 32);
            LDSM_X4T(bl[0], bl[1], bl[2], bl[3], bOffL + buf * 4352 + np * 32);
            mma16816(acc[0][np * 2],     ah[0], bh[0], bh[1]);
            mma16816(acc[0][np * 2 + 1], ah[0], bh[2], bh[3]);
            mma16816(acc[1][np * 2],     ah[1], bh[0], bh[1]);
            mma16816(acc[1][np * 2 + 1], ah[1], bh[2], bh[3]);
            mma16816(acc[0][np * 2],     ah[0], bl[0], bl[1]);
            mma16816(acc[0][np * 2 + 1], ah[0], bl[2], bl[3]);
            mma16816(acc[1][np * 2],     ah[1], bl[0], bl[1]);
            mma16816(acc[1][np * 2 + 1], ah[1], bl[2], bl[3]);
            mma16816(acc[0][np * 2],     al[0], bh[0], bh[1]);
            mma16816(acc[0][np * 2 + 1], al[0], bh[2], bh[3]);
            mma16816(acc[1][np * 2],     al[1], bh[0], bh[1]);
            mma16816(acc[1][np * 2 + 1], al[1], bh[2], bh[3]);
        }
        buf ^= 1;
    }

    const int g = lane >> 2, q = (lane & 3) * 2;
#pragma unroll
    for (int mt = 0; mt < 2; mt++) {
        int r0loc = wm * 32 + mt * 16 + g;
        float d0 = aux[r0loc], d1 = aux[r0loc + 8];
#pragma unroll
        for (int nt = 0; nt < 8; nt++) {
            const float* a = acc[mt][nt];
            int col = bcol + wn * 64 + nt * 8 + q;
            size_t r0 = brow + r0loc;
            *(float2*)&C[r0 * KXL + col]       = make_float2(a[0] * d0, a[1] * d0);
            *(float2*)&C[(r0 + 8) * KXL + col] = make_float2(a[2] * d1, a[3] * d1);
        }
    }
#undef LOADG0
#undef STORES0
}

// ---------------- gemm1 fused LN + label_out (merged grid, R16) ----------------
__global__ void __launch_bounds__(256, 2) gemm1_fused(
    const float* __restrict__ Hm, const float* __restrict__ Yc,
    const bf16* __restrict__ Bh, const bf16* __restrict__ Bl,
    const float* __restrict__ gam, const float* __restrict__ bet,
    const float* __restrict__ W2, const float* __restrict__ b2,
    const float* __restrict__ g2, const float* __restrict__ be2,
    float* __restrict__ C, float* __restrict__ outL)
{
    extern __shared__ char sm[];
    const int t = threadIdx.x, lane = t & 31, wid = t >> 5;

    if (blockIdx.x >= 1024) {
        float* W2s = (float*)(sm);
        float* las = (float*)(sm + 16384);
        const int w = wid, l = lane;
#pragma unroll
        for (int i = 0; i < 4; i++) {
            int idx = t + i * 256;
            ((float4*)W2s)[idx] = ((const float4*)W2)[idx];
        }
        size_t row = (size_t)(blockIdx.x - 1024) * 8 + w;
        const float* hrow = Hm + row * KXL + HX;
        las[w * 64 + l] = hrow[l];
        las[w * 64 + l + 32] = hrow[l + 32];
        __syncthreads();
        float acc0 = 0.f, acc1 = 0.f;
#pragma unroll
        for (int k = 0; k < 64; k++) {
            float v = las[w * 64 + k];
            acc0 = fmaf(v, W2s[k * 64 + l], acc0);
            acc1 = fmaf(v, W2s[k * 64 + l + 32], acc1);
        }
        acc0 = fmaxf(acc0 + b2[l], 0.f);
        acc1 = fmaxf(acc1 + b2[l + 32], 0.f);
        float mean = warp_sum(acc0 + acc1) * (1.0f / 64.0f);
        float sq = warp_sum(acc0 * acc0 + acc1 * acc1) * (1.0f / 64.0f);
        float r = rsqrtf(sq - mean * mean + 1e-5f);
        outL[row * HL + l]      = (acc0 - mean) * r * g2[l] + be2[l];
        outL[row * HL + l + 32] = (acc1 - mean) * r * g2[l + 32] + be2[l + 32];
        return;
    }

    bf16* AsH = (bf16*)(sm);
    bf16* AsL = (bf16*)(sm + 6144);
    bf16* BsH = (bf16*)(sm + 12288);
    bf16* BsL = (bf16*)(sm + 29184);
    float* bias_s = (float*)(sm + 46080);
    float* gam_s  = (float*)(sm + 47104);
    float* bet_s  = (float*)(sm + 48128);
    float* rsum   = (float*)(sm + 49152);
    float* rsq    = (float*)(sm + 50176);
    float* mstd   = (float*)(sm + 51200);

    const int wm = wid >> 2, wn = wid & 3;
    const size_t brow = (size_t)blockIdx.x * 64;
    const size_t batch = brow >> 7;

    if (t < 256) {
        bias_s[t] = Yc[batch * 256 + t];
        gam_s[t] = gam[t];
        bet_s[t] = bet[t];
    }

    const uint32_t aOffH = smem_u32(AsH) + ((wm * 32 + (lane & 15)) * 24 + (lane >> 4) * 8) * 2;
    const uint32_t aOffL = aOffH + 6144;
    const uint32_t bOffH = smem_u32(BsH) + ((lane & 15) * 264 + wn * 64 + ((lane >> 4) << 3)) * 2;
    const uint32_t bOffL = bOffH + 16896;

    float acc[2][8][4] = {};
    float4 pa;
    uint4 pbh[2], pbl[2];
    const int arL = t >> 2, ac4 = (t & 3) * 4;
    const int bk = t >> 5, bn8 = (t & 31) * 8;

#define LOADG1(k0) do {                                                       \
        pa = *(const float4*)(Hm + (brow + arL) * (size_t)KXL + (k0) + ac4);  \
        _Pragma("unroll")                                                     \
        for (int j = 0; j < 2; j++) {                                         \
            int k = bk + j * 8;                                               \
            pbh[j] = *(const uint4*)(Bh + (size_t)((k0) + k) * 256 + bn8);    \
            pbl[j] = *(const uint4*)(Bl + (size_t)((k0) + k) * 256 + bn8);    \
        }                                                                     \
    } while (0)

#define STORES1(buf) do {                                                     \
        uint2 ph, pl;                                                         \
        split2(pa.x, pa.y, ph.x, pl.x); split2(pa.z, pa.w, ph.y, pl.y);       \
        *(uint2*)(AsH + (buf) * 1536 + arL * 24 + ac4) = ph;                  \
        *(uint2*)(AsL + (buf) * 1536 + arL * 24 + ac4) = pl;                  \
        _Pragma("unroll")                                                     \
        for (int j = 0; j < 2; j++) {                                         \
            int k = bk + j * 8;                                               \
            *(uint4*)(BsH + (buf) * 4224 + k * 264 + bn8) = pbh[j];           \
            *(uint4*)(BsL + (buf) * 4224 + k * 264 + bn8) = pbl[j];           \
        }                                                                     \
    } while (0)

    LOADG1(0);
    int buf = 0;
#pragma unroll 1
    for (int c = 0; c < 20; c++) {
        STORES1(buf);
        if (c + 1 < 20) LOADG1((c + 1) * 16);
        __syncthreads();
        uint32_t ah[2][4], al[2][4];
#pragma unroll
        for (int mt = 0; mt < 2; mt++) {
            LDSM_X4(ah[mt][0], ah[mt][1], ah[mt][2], ah[mt][3], aOffH + buf * 3072 + mt * 768);
            LDSM_X4(al[mt][0], al[mt][1], al[mt][2], al[mt][3], aOffL + buf * 3072 + mt * 768);
        }
#pragma unroll
        for (int np = 0; np < 4; np++) {
            uint32_t bh[4], bl[4];
            LDSM_X4T(bh[0], bh[1], bh[2], bh[3], bOffH + buf * 8448 + np * 32);
            LDSM_X4T(bl[0], bl[1], bl[2], bl[3], bOffL + buf * 8448 + np * 32);
            mma16816(acc[0][np * 2],     ah[0], bh[0], bh[1]);
            mma16816(acc[0][np * 2 + 1], ah[0], bh[2], bh[3]);
            mma16816(acc[1][np * 2],     ah[1], bh[0], bh[1]);
            mma16816(acc[1][np * 2 + 1], ah[1], bh[2], bh[3]);
            mma16816(acc[0][np * 2],     ah[0], bl[0], bl[1]);
            mma16816(acc[0][np * 2 + 1], ah[0], bl[2], bl[3]);
            mma16816(acc[1][np * 2],     ah[1], bl[0], bl[1]);
            mma16816(acc[1][np * 2 + 1], ah[1], bl[2], bl[3]);
            mma16816(acc[0][np * 2],     al[0], bh[0], bh[1]);
            mma16816(acc[0][np * 2 + 1], al[0], bh[2], bh[3]);
            mma16816(acc[1][np * 2],     al[1], bh[0], bh[1]);
            mma16816(acc[1][np * 2 + 1], al[1], bh[2], bh[3]);
        }
        buf ^= 1;
    }

    const int g = lane >> 2, q = (lane & 3) * 2;
#pragma unroll
    for (int mt = 0; mt < 2; mt++) {
#pragma unroll
        for (int hf = 0; hf < 2; hf++) {
            float s = 0.f, qq = 0.f;
#pragma unroll
            for (int nt = 0; nt < 8; nt++) {
                int col = wn * 64 + nt * 8 + q;
                float v0 = fmaxf(acc[mt][nt][hf * 2]     + bias_s[col],     0.f);
                float v1 = fmaxf(acc[mt][nt][hf * 2 + 1] + bias_s[col + 1], 0.f);
                s += v0 + v1; qq += v0 * v0 + v1 * v1;
            }
            s  += __shfl_xor_sync(0xffffffffu, s, 1);
            s  += __shfl_xor_sync(0xffffffffu, s, 2);
            qq += __shfl_xor_sync(0xffffffffu, qq, 1);
            qq += __shfl_xor_sync(0xffffffffu, qq, 2);
            if ((lane & 3) == 0) {
                int row = wm * 32 + mt * 16 + hf * 8 + g;
                rsum[row * 4 + wn] = s;
                rsq [row * 4 + wn] = qq;
            }
        }
    }
    __syncthreads();
    if (t < 64) {
        float S = rsum[t * 4] + rsum[t * 4 + 1] + rsum[t * 4 + 2] + rsum[t * 4 + 3];
        float Q = rsq [t * 4] + rsq [t * 4 + 1] + rsq [t * 4 + 2] + rsq [t * 4 + 3];
        float mean = S * (1.0f / 256.0f);
        float var  = Q * (1.0f / 256.0f) - mean * mean;
        mstd[t * 2]     = mean;
        mstd[t * 2 + 1] = rsqrtf(var + 1e-5f);
    }
    __syncthreads();
#pragma unroll
    for (int mt = 0; mt < 2; mt++)
#pragma unroll
        for (int nt = 0; nt < 8; nt++) {
            const float* a = acc[mt][nt];
            int col = wn * 64 + nt * 8 + q;
            float b0 = bias_s[col], b1 = bias_s[col + 1];
            float g0 = gam_s[col],  g1 = gam_s[col + 1];
            float e0 = bet_s[col],  e1 = bet_s[col + 1];
            int r0 = wm * 32 + mt * 16 + g;
            float m0 = mstd[r0 * 2], s0 = mstd[r0 * 2 + 1];
            float m1 = mstd[(r0 + 8) * 2], s1 = mstd[(r0 + 8) * 2 + 1];
            float v0 = fmaxf(a[0] + b0, 0.f), v1 = fmaxf(a[1] + b1, 0.f);
            float v2 = fmaxf(a[2] + b0, 0.f), v3 = fmaxf(a[3] + b1, 0.f);
            *(float2*)&C[(brow + r0) * (size_t)HX + col] =
                make_float2((v0 - m0) * s0 * g0 + e0, (v1 - m0) * s0 * g1 + e1);
            *(float2*)&C[(brow + r0 + 8) * (size_t)HX + col] =
                make_float2((v2 - m1) * s1 * g0 + e0, (v3 - m1) * s1 * g1 + e1);
        }
#undef LOADG1
#undef STORES1
}

// ---------------- batched (A+I) MMA GEMM: 128x80 block, K-chunk 32 (R12) -----------
__global__ void __launch_bounds__(256, 2) an_mma(
    const unsigned* __restrict__ mask, const float* __restrict__ dinv,
    const float* __restrict__ T,
    const float* __restrict__ bx, const float* __restrict__ bl,
    float* __restrict__ H)
{
    extern __shared__ char sm[];
    bf16* As  = (bf16*)(sm);
    bf16* BsH = (bf16*)(sm + 34816);
    bf16* BsL = (bf16*)(sm + 46080);
    float* bias_s = (float*)(sm + 57344);
    float* dinv_s = (float*)(sm + 57664);

    const int t = threadIdx.x, lane = t & 31, wid = t >> 5;
    const int ct = blockIdx.x, b = blockIdx.y;
    const float* Tb = T + (size_t)b * 128 * KXL + ct * 80;

#pragma unroll
    for (int j = 0; j < 2; j++) {
        int idx = t + j * 256;
        int i = idx >> 2, jg = idx & 3;
        unsigned m = mask[((size_t)b * 128 + i) * 4 + jg];
        uint32_t* dst = (uint32_t*)(As + i * 136 + jg * 32);
#pragma unroll
        for (int p = 0; p < 16; p++) {
            int j0 = jg * 32 + p * 2;
            uint32_t s0 = ((m >> (p * 2)) & 1u) + (j0 == i);
            uint32_t s1 = ((m >> (p * 2 + 1)) & 1u) + (j0 + 1 == i);
            uint32_t v0 = (s0 == 0) ? 0u : ((s0 == 1) ? 0x3F80u : 0x4000u);
            uint32_t v1 = (s1 == 0) ? 0u : ((s1 == 1) ? 0x3F80u : 0x4000u);
            dst[p] = v0 | (v1 << 16);
        }
    }
    if (t < 80) {
        int gcol = ct * 80 + t;
        bias_s[t] = (gcol < 256) ? bx[gcol] : bl[gcol - 256];
    }
    if (t >= 128 && t < 256) dinv_s[t - 128] = dinv[(size_t)b * 128 + (t - 128)];

    const uint32_t aOff = smem_u32(As) + ((wid * 16 + (lane & 15)) * 136 + (lane >> 4) * 8) * 2;
    const uint32_t bOffH = smem_u32(BsH) + ((lane & 15) * 88 + ((lane >> 4) << 3)) * 2;
    const uint32_t bOffL = smem_u32(BsL) + ((lane & 15) * 88 + ((lane >> 4) << 3)) * 2;

    float acc[10][4] = {};
    float4 pb[3];
    const int k_0 = t / 20,           c4_0 = t % 20;
    const int k_1 = (t + 256) / 20,   c4_1 = (t + 256) % 20;
    const int k_2 = (t + 512) / 20,   c4_2 = (t + 512) % 20;
    const bool v2 = (t < 128);

#define BLOAD(k0) do {                                                        \
        pb[0] = *(const float4*)(Tb + (size_t)((k0) + k_0) * KXL + c4_0 * 4); \
        pb[1] = *(const float4*)(Tb + (size_t)((k0) + k_1) * KXL + c4_1 * 4); \
        if (v2) pb[2] = *(const float4*)(Tb + (size_t)((k0) + k_2) * KXL + c4_2 * 4); \
    } while (0)

#define BSTORE(buf) do {                                                      \
        uint32_t h0, l0, h1, l1;                                              \
        split2(pb[0].x, pb[0].y, h0, l0); split2(pb[0].z, pb[0].w, h1, l1);   \
        *(uint2*)(BsH + (buf) * 2816 + k_0 * 88 + c4_0 * 4) = make_uint2(h0, h1); \
        *(uint2*)(BsL + (buf) * 2816 + k_0 * 88 + c4_0 * 4) = make_uint2(l0, l1); \
        split2(pb[1].x, pb[1].y, h0, l0); split2(pb[1].z, pb[1].w, h1, l1);   \
        *(uint2*)(BsH + (buf) * 2816 + k_1 * 88 + c4_1 * 4) = make_uint2(h0, h1); \
        *(uint2*)(BsL + (buf) * 2816 + k_1 * 88 + c4_1 * 4) = make_uint2(l0, l1); \
        if (v2) {                                                             \
            split2(pb[2].x, pb[2].y, h0, l0); split2(pb[2].z, pb[2].w, h1, l1); \
            *(uint2*)(BsH + (buf) * 2816 + k_2 * 88 + c4_2 * 4) = make_uint2(h0, h1); \
            *(uint2*)(BsL + (buf) * 2816 + k_2 * 88 + c4_2 * 4) = make_uint2(l0, l1); \
        }                                                                     \
    } while (0)

    BLOAD(0);
    int buf = 0;
#pragma unroll 1
    for (int c = 0; c < 4; c++) {
        BSTORE(buf);
        if (c + 1 < 4) BLOAD((c + 1) * 32);
        __syncthreads();
#pragma unroll
        for (int ks = 0; ks < 2; ks++) {
            uint32_t a[4];
            LDSM_X4(a[0], a[1], a[2], a[3], aOff + (c * 2 + ks) * 32);
#pragma unroll
            for (int pr = 0; pr < 2; pr++) {
                uint32_t bh0[4], bl0[4], bh1[4], bl1[4];
                uint32_t base = buf * 5632 + ks * 2816 + pr * 64;
                LDSM_X4T(bh0[0], bh0[1], bh0[2], bh0[3], bOffH + base);
                LDSM_X4T(bl0[0], bl0[1], bl0[2], bl0[3], bOffL + base);
                LDSM_X4T(bh1[0], bh1[1], bh1[2], bh1[3], bOffH + base + 32);
                LDSM_X4T(bl1[0], bl1[1], bl1[2], bl1[3], bOffL + base + 32);
                float* a0 = acc[pr * 4 + 0];
                float* a1 = acc[pr * 4 + 1];
                float* a2 = acc[pr * 4 + 2];
                float* a3 = acc[pr * 4 + 3];
                mma16816(a0, a, bh0[0], bh0[1]);
                mma16816(a1, a, bh0[2], bh0[3]);
                mma16816(a2, a, bh1[0], bh1[1]);
                mma16816(a3, a, bh1[2], bh1[3]);
                mma16816(a0, a, bl0[0], bl0[1]);
                mma16816(a1, a, bl0[2], bl0[3]);
                mma16816(a2, a, bl1[0], bl1[1]);
                mma16816(a3, a, bl1[2], bl1[3]);
            }
            {
                uint32_t bh[4], blr[4];
                uint32_t base = buf * 5632 + ks * 2816 + 4 * 32;
                LDSM_X4T(bh[0], bh[1], bh[2], bh[3], bOffH + base);
                LDSM_X4T(blr[0], blr[1], blr[2], blr[3], bOffL + base);
                mma16816(acc[8], a, bh[0], bh[1]);
                mma16816(acc[9], a, bh[2], bh[3]);
                mma16816(acc[8], a, blr[0], blr[1]);
                mma16816(acc[9], a, blr[2], blr[3]);
            }
        }
        buf ^= 1;
    }

    const int g = lane >> 2, q = (lane & 3) * 2;
    const int r0loc = wid * 16 + g;
    const float d0 = dinv_s[r0loc], d1 = dinv_s[r0loc + 8];
#pragma unroll
    for (int nt = 0; nt < 10; nt++) {
        const float* a = acc[nt];
        int lcol = nt * 8 + q;
        int gcol = ct * 80 + lcol;
        float b0 = bias_s[lcol], b1 = bias_s[lcol + 1];
        size_t r0 = (size_t)b * 128 + r0loc;
        *(float2*)&H[r0 * KXL + gcol] =
            make_float2(fmaf(a[0], d0, b0), fmaf(a[1], d0, b1));
        *(float2*)&H[(r0 + 8) * KXL + gcol] =
            make_float2(fmaf(a[2], d1, b0), fmaf(a[3], d1, b1));
    }
#undef BLOAD
#undef BSTORE
}

// ---------------- label@Wl via MMA: 128x64 block, K=64, dinv-scaled (R12) ----------
__global__ void __launch_bounds__(256) sgemm64_mma(
    const float* __restrict__ A, const bf16* __restrict__ Wlh,
    const bf16* __restrict__ Wll, const float* __restrict__ dinv,
    float* __restrict__ C)
{
    __shared__ __align__(16) bf16 AsH[2 * 3072];
    __shared__ __align__(16) bf16 AsL[2 * 3072];
    __shared__ __align__(16) bf16 BsH[2 * 1152];
    __shared__ __align__(16) bf16 BsL[2 * 1152];
    __shared__ float dinv_s[128];

    const int t = threadIdx.x, lane = t & 31, wid = t >> 5;
    const size_t brow = (size_t)blockIdx.x * 128;
    if (t < 128) dinv_s[t] = dinv[brow + t];

    const uint32_t aOffH = smem_u32(AsH) + ((wid * 16 + (lane & 15)) * 24 + (lane >> 4) * 8) * 2;
    const uint32_t aOffL = smem_u32(AsL) + ((wid * 16 + (lane & 15)) * 24 + (lane >> 4) * 8) * 2;
    const uint32_t bOffH = smem_u32(BsH) + ((lane & 15) * 72 + ((lane >> 4) << 3)) * 2;
    const uint32_t bOffL = smem_u32(BsL) + ((lane & 15) * 72 + ((lane >> 4) << 3)) * 2;

    float acc[8][4] = {};
    float4 pa[2];
    uint4 pb;
    const int ar0 = t >> 2, ac0 = (t & 3) * 4;
    const int ar1 = (t + 256) >> 2, ac1 = ((t + 256) & 3) * 4;
    const int bpl = t >> 7, bkr = (t & 127) >> 3, bc8 = (t & 7) * 8;

#define SLOAD(k0) do {                                                        \
        pa[0] = *(const float4*)(A + (brow + ar0) * 64 + (k0) + ac0);         \
        pa[1] = *(const float4*)(A + (brow + ar1) * 64 + (k0) + ac1);         \
        const bf16* wsrc = bpl ? Wll : Wlh;                                   \
        pb = *(const uint4*)(wsrc + (size_t)((k0) + bkr) * 64 + bc8);         \
    } while (0)

#define SSTORE(buf) do {                                                      \
        uint32_t h0, l0, h1, l1;                                              \
        split2(pa[0].x, pa[0].y, h0, l0); split2(pa[0].z, pa[0].w, h1, l1);   \
        *(uint2*)(AsH + (buf) * 3072 + ar0 * 24 + ac0) = make_uint2(h0, h1);  \
        *(uint2*)(AsL + (buf) * 3072 + ar0 * 24 + ac0) = make_uint2(l0, l1);  \
        split2(pa[1].x, pa[1].y, h0, l0); split2(pa[1].z, pa[1].w, h1, l1);   \
        *(uint2*)(AsH + (buf) * 3072 + ar1 * 24 + ac1) = make_uint2(h0, h1);  \
        *(uint2*)(AsL + (buf) * 3072 + ar1 * 24 + ac1) = make_uint2(l0, l1);  \
        bf16* wdst = bpl ? BsL : BsH;                                         \
        *(uint4*)(wdst + (buf) * 1152 + bkr * 72 + bc8) = pb;                 \
    } while (0)

    SLOAD(0);
    int buf = 0;
#pragma unroll 1
    for (int c = 0; c < 4; c++) {
        SSTORE(buf);
        if (c + 1 < 4) SLOAD((c + 1) * 16);
        __syncthreads();
        uint32_t ah[4], al[4];
        LDSM_X4(ah[0], ah[1], ah[2], ah[3], aOffH + buf * 6144);
        LDSM_X4(al[0], al[1], al[2], al[3], aOffL + buf * 6144);
#pragma unroll
        for (int np = 0; np < 4; np++) {
            uint32_t bh[4], blr[4];
            LDSM_X4T(bh[0], bh[1], bh[2], bh[3], bOffH + buf * 2304 + np * 32);
            LDSM_X4T(blr[0], blr[1], blr[2], blr[3], bOffL + buf * 2304 + np * 32);
            mma16816(acc[np * 2],     ah, bh[0], bh[1]);
            mma16816(acc[np * 2 + 1], ah, bh[2], bh[3]);
            mma16816(acc[np * 2],     ah, blr[0], blr[1]);
            mma16816(acc[np * 2 + 1], ah, blr[2], blr[3]);
            mma16816(acc[np * 2],     al, bh[0], bh[1]);
            mma16816(acc[np * 2 + 1], al, bh[2], bh[3]);
        }
        buf ^= 1;
    }

    const int g = lane >> 2, q = (lane & 3) * 2;
    const int r0loc = wid * 16 + g;
    const float d0 = dinv_s[r0loc], d1 = dinv_s[r0loc + 8];
#pragma unroll
    for (int nt = 0; nt < 8; nt++) {
        const float* a = acc[nt];
        int col = nt * 8 + q;
        size_t r0 = brow + r0loc;
        *(float2*)&C[r0 * KXL + 256 + col]       = make_float2(a[0] * d0, a[1] * d0);
        *(float2*)&C[(r0 + 8) * KXL + 256 + col] = make_float2(a[2] * d1, a[3] * d1);
    }
#undef SLOAD
#undef SSTORE
}

// ---------------- launcher ----------------
extern "C" void kernel_launch(void* const* d_in, const int* in_sizes, int n_in,
                              void* d_out, int out_size) {
    const float* X     = (const float*)d_in[0];
    const int*   E     = (const int*)d_in[1];
    const float* y     = (const float*)d_in[2];
    const float* label = (const float*)d_in[3];
    const float* Wx  = (const float*)d_in[5];
    const float* bx  = (const float*)d_in[6];
    const float* Wl  = (const float*)d_in[7];
    const float* bl  = (const float*)d_in[8];
    const float* W1  = (const float*)d_in[9];
    const float* b1  = (const float*)d_in[10];
    const float* g1  = (const float*)d_in[11];
    const float* be1 = (const float*)d_in[12];
    const float* W2  = (const float*)d_in[13];
    const float* b2  = (const float*)d_in[14];
    const float* g2  = (const float*)d_in[15];
    const float* be2 = (const float*)d_in[16];
    float* out_X = (float*)d_out;
    float* out_L = out_X + (size_t)ROWS * HX;

    float *pdinv, *pT, *pH, *pYc;
    unsigned* pmask;
    bf16 *pWxh, *pWxl, *pW1h, *pW1l, *pWlh, *pWll;
    cudaGetSymbolAddress((void**)&pdinv, g_dinv);
    cudaGetSymbolAddress((void**)&pmask, g_mask);
    cudaGetSymbolAddress((void**)&pT,    g_T);
    cudaGetSymbolAddress((void**)&pH,    g_H);
    cudaGetSymbolAddress((void**)&pYc,   g_Yc);
    cudaGetSymbolAddress((void**)&pWxh,  g_Wxh);
    cudaGetSymbolAddress((void**)&pWxl,  g_Wxl);
    cudaGetSymbolAddress((void**)&pW1h,  g_W1h);
    cudaGetSymbolAddress((void**)&pW1l,  g_W1l);
    cudaGetSymbolAddress((void**)&pWlh,  g_Wlh);
    cudaGetSymbolAddress((void**)&pWll,  g_Wll);

    const int SMEM0 = 42496;
    const int SMEM1 = 51712;
    const int SMEMA = 58176;
    cudaFuncSetAttribute(gemm0_mma,   cudaFuncAttributeMaxDynamicSharedMemorySize, SMEM0);
    cudaFuncSetAttribute(gemm1_fused, cudaFuncAttributeMaxDynamicSharedMemorySize, SMEM1);
    cudaFuncSetAttribute(an_mma,      cudaFuncAttributeMaxDynamicSharedMemorySize, SMEMA);

    prep_all_kernel<<<8192 + 656 + 512, 256>>>(E, pdinv, pmask, Wx, W1, Wl, y, b1,
                                               pWxh, pWxl, pW1h, pW1l, pWlh, pWll, pYc);

    gemm0_mma<<<dim3(2, 512), 256, SMEM0>>>(X, label, pWxh, pWxl, pdinv, pT);
    sgemm64_mma<<<512, 256>>>(label, pWlh, pWll, pdinv, pT);

    an_mma<<<dim3(4, BSZ), 256, SMEMA>>>(pmask, pdinv, pT, bx, bl, pH);

    gemm1_fused<<<1024 + ROWS / 8, 256, SMEM1>>>(pH, pYc, pW1h, pW1l, g1, be1,
                                                 W2, b2, g2, be2, out_X, out_L);
}